// round 6
// baseline (speedup 1.0000x reference)
#include <cuda_runtime.h>
#include <cuda_bf16.h>
#include <math.h>
#include <stdint.h>

#define BATCH 8
#define SEQ   2048
#define DIM   1024
#define MTOT  (BATCH * SEQ)   // 16384

#define NBF ((size_t)MTOT * DIM)         // 16,777,216
#define NSC ((size_t)BATCH * SEQ * SEQ)  // 33,554,432

// ===================== scratch (no cudaMalloc allowed) =====================
__device__ __align__(1024) __nv_bfloat16 g_Qh[NBF], g_Ql[NBF];   // split inputs
__device__ __align__(1024) __nv_bfloat16 g_Kh[NBF], g_Kl[NBF];
__device__ __align__(1024) __nv_bfloat16 g_Vh[NBF], g_Vl[NBF];
__device__ __align__(1024) __nv_bfloat16 g_qph[NBF], g_qpl[NBF]; // q projection
__device__ __align__(1024) __nv_bfloat16 g_kph[NBF], g_kpl[NBF]; // k projection
__device__ __align__(1024) __nv_bfloat16 g_vph[NBF], g_vpl[NBF]; // v projection [s][d]
__device__ __align__(1024) __nv_bfloat16 g_gch[NBF], g_gcl[NBF]; // gated context
__device__ __align__(1024) __nv_bfloat16 g_ah[NSC], g_al[NSC];   // softmax(attn)
__device__ __align__(1024) __nv_bfloat16 g_W[10][DIM * DIM];     // W h/l x5, layout [k][n]
__device__ __align__(1024) float g_scores[NSC];
__device__ __align__(1024) float g_gpre[NBF];

// ===================== PTX wrappers (baseline sm_80+ features only) =========
__device__ __forceinline__ uint32_t smem_u32(const void* p) {
    uint32_t a;
    asm("{ .reg .u64 t; cvta.to.shared.u64 t, %1; cvt.u32.u64 %0, t; }" : "=r"(a) : "l"(p));
    return a;
}
__device__ __forceinline__ void cpa16(uint32_t dst, const void* src) {
    asm volatile("cp.async.cg.shared.global [%0], [%1], 16;" :: "r"(dst), "l"(src));
}
__device__ __forceinline__ void cp_commit() {
    asm volatile("cp.async.commit_group;" ::: "memory");
}
template <int N>
__device__ __forceinline__ void cp_wait() {
    asm volatile("cp.async.wait_group %0;" :: "n"(N) : "memory");
}
__device__ __forceinline__ void ldm4(uint32_t r[4], uint32_t addr) {
    asm volatile("ldmatrix.sync.aligned.m8n8.x4.shared.b16 {%0,%1,%2,%3}, [%4];"
                 : "=r"(r[0]), "=r"(r[1]), "=r"(r[2]), "=r"(r[3]) : "r"(addr));
}
__device__ __forceinline__ void ldm4t(uint32_t r[4], uint32_t addr) {
    asm volatile("ldmatrix.sync.aligned.m8n8.x4.trans.shared.b16 {%0,%1,%2,%3}, [%4];"
                 : "=r"(r[0]), "=r"(r[1]), "=r"(r[2]), "=r"(r[3]) : "r"(addr));
}
__device__ __forceinline__ void mma16816(float c[4],
                                         const uint32_t a[4],
                                         uint32_t b0, uint32_t b1) {
    asm volatile(
        "mma.sync.aligned.m16n8k16.row.col.f32.bf16.bf16.f32 "
        "{%0,%1,%2,%3}, {%4,%5,%6,%7}, {%8,%9}, {%0,%1,%2,%3};"
        : "+f"(c[0]), "+f"(c[1]), "+f"(c[2]), "+f"(c[3])
        : "r"(a[0]), "r"(a[1]), "r"(a[2]), "r"(a[3]), "r"(b0), "r"(b1));
}
__device__ __forceinline__ void split2(float x, __nv_bfloat16& h, __nv_bfloat16& l) {
    h = __float2bfloat16(x);
    l = __float2bfloat16(x - __bfloat162float(h));
}

// ===================== bf16x3 HMMA GEMM =====================
// CTA tile 256(m) x 128(n), 256 threads / 8 warps, warp tile 64x64.
// 3-stage cp.async pipeline, one __syncthreads per K-chunk (kc=32).
// D = A @ op(B), fp32 accumulate, 3 MMA passes (hh + hl + lh).
// TRANSB=false: B stored [n][k]. TRANSB=true: B stored [k][n].
// OMODE 0: fp32 out (+bias).
// OMODE 1: bf16 hi/lo pair out (+bias).
// OMODE 2: gated bf16 hi/lo out: val * sigmoid(gpre) (gpre passed via cf).
#define PA_E   40            // A / B-nontrans row pitch (elems): 32 data + 8 pad
#define PA_B   (PA_E * 2)    // 80 bytes
#define PBT_E  136           // B-trans row pitch (elems): 128 data + 8 pad
#define PBT_B  (PBT_E * 2)   // 272 bytes
#define A_MAT  20480         // 256 rows x 80 B
#define B_MAT  10240         // 128 rows x 80 B (or 32 x 272 = 8704, padded region)
#define STAGE_BYTES (2 * A_MAT + 2 * B_MAT)   // 61440
#define NSTAGE 3
#define GEMM_SMEM (NSTAGE * STAGE_BYTES)      // 184320

template <bool TRANSB, int OMODE>
__global__ void __launch_bounds__(256, 1)
hgemm(const __nv_bfloat16* __restrict__ gAh, const __nv_bfloat16* __restrict__ gAl,
      const __nv_bfloat16* __restrict__ gBh, const __nv_bfloat16* __restrict__ gBl,
      const float* __restrict__ cf_or_gpre,   // OMODE0: out fp32. OMODE2: gpre in.
      __nv_bfloat16* __restrict__ ch, __nv_bfloat16* __restrict__ cl,
      const float* __restrict__ bias,
      int lda, int ldb, int ldc, int K,
      long long sa, long long sb, long long sc)
{
    extern __shared__ __align__(128) char smem[];
    const uint32_t sbase = smem_u32(smem);

    const int tid  = threadIdx.x;
    const int wid  = tid >> 5;
    const int lane = tid & 31;
    const int m0   = blockIdx.y * 256;
    const int n0   = blockIdx.x * 128;
    const int z    = blockIdx.z;

    gAh += (long long)z * sa;  gAl += (long long)z * sa;
    gBh += (long long)z * sb;  gBl += (long long)z * sb;

    const int wm0 = (wid >> 1) * 64;    // warp m offset (0..192)
    const int wn0 = (wid & 1) * 64;     // warp n offset (0/64)

    float acc[4][8][4];
    #pragma unroll
    for (int i = 0; i < 4; i++)
        #pragma unroll
        for (int j = 0; j < 8; j++)
            #pragma unroll
            for (int r = 0; r < 4; r++) acc[i][j][r] = 0.0f;

    const int nchunks = K >> 5;

    // ------- stage loader (256 threads) -------
    auto load_stage = [&](int s, int k0) {
        const uint32_t st = sbase + s * STAGE_BYTES;
        // A hi/lo: 256 rows x 32 cols -> 1024 x 16B chunks, 4 per thread
        #pragma unroll
        for (int j = 0; j < 4; j++) {
            const int c = tid + 256 * j;
            const int row = c >> 2, col = c & 3;
            const uint32_t so = st + row * PA_B + col * 16;
            const long long go = (long long)(m0 + row) * lda + k0 + col * 8;
            cpa16(so,         gAh + go);
            cpa16(so + A_MAT, gAl + go);
        }
        // B hi/lo: 512 x 16B chunks, 2 per thread
        const uint32_t bst = st + 2 * A_MAT;
        #pragma unroll
        for (int j = 0; j < 2; j++) {
            const int c = tid + 256 * j;
            if (TRANSB) {   // B: 32 rows (k) x 128 cols (n)
                const int row = c >> 4, col = c & 15;
                const uint32_t so = bst + row * PBT_B + col * 16;
                const long long go = (long long)(k0 + row) * ldb + n0 + col * 8;
                cpa16(so,         gBh + go);
                cpa16(so + B_MAT, gBl + go);
            } else {        // B: 128 rows (n) x 32 cols (k)
                const int row = c >> 2, col = c & 3;
                const uint32_t so = bst + row * PA_B + col * 16;
                const long long go = (long long)(n0 + row) * ldb + k0 + col * 8;
                cpa16(so,         gBh + go);
                cpa16(so + B_MAT, gBl + go);
            }
        }
    };

    // ------- compute one stage -------
    auto compute_stage = [&](int s) {
        const uint32_t ab = sbase + s * STAGE_BYTES;
        const uint32_t bb = ab + 2 * A_MAT;
        #pragma unroll
        for (int ks = 0; ks < 32; ks += 16) {
            uint32_t ah[4][4], al[4][4];
            #pragma unroll
            for (int im = 0; im < 4; im++) {
                const uint32_t addr = ab
                    + (wm0 + im * 16 + (lane & 15)) * PA_B
                    + (ks + ((lane >> 4) << 3)) * 2;
                ldm4(ah[im], addr);
                ldm4(al[im], addr + A_MAT);
            }
            #pragma unroll
            for (int half = 0; half < 4; half++) {   // n-tiles 2*half, 2*half+1
                const int nb = wn0 + half * 16;
                uint32_t rh[4], rl[4];
                if (TRANSB) {
                    const int krow = ks + (lane & 7) + (((lane >> 3) & 1) << 3);
                    const int ncol = nb + ((lane >> 4) << 3);
                    const uint32_t addr = bb + krow * PBT_B + ncol * 2;
                    ldm4t(rh, addr);
                    ldm4t(rl, addr + B_MAT);
                } else {
                    const int nrow = nb + (lane & 7) + ((lane >> 4) << 3);
                    const int kcol = ks + (((lane >> 3) & 1) << 3);
                    const uint32_t addr = bb + nrow * PA_B + kcol * 2;
                    ldm4(rh, addr);
                    ldm4(rl, addr + B_MAT);
                }
                #pragma unroll
                for (int im = 0; im < 4; im++) {
                    mma16816(acc[im][2*half],   ah[im], rh[0], rh[1]);
                    mma16816(acc[im][2*half],   ah[im], rl[0], rl[1]);
                    mma16816(acc[im][2*half],   al[im], rh[0], rh[1]);
                    mma16816(acc[im][2*half+1], ah[im], rh[2], rh[3]);
                    mma16816(acc[im][2*half+1], ah[im], rl[2], rl[3]);
                    mma16816(acc[im][2*half+1], al[im], rh[2], rh[3]);
                }
            }
        }
    };

    // ------- 3-stage pipeline, single sync per chunk -------
    load_stage(0, 0);  cp_commit();
    if (nchunks > 1) { load_stage(1, 32); cp_commit(); }
    for (int c = 0; c < nchunks; c++) {
        if (c + 2 < nchunks) cp_wait<1>(); else cp_wait<0>();
        __syncthreads();
        if (c + 2 < nchunks) { load_stage((c + 2) % NSTAGE, (c + 2) * 32); cp_commit(); }
        compute_stage(c % NSTAGE);
    }

    // ------- epilogue: write from fragments -------
    const long long zc = (long long)z * sc;
    #pragma unroll
    for (int im = 0; im < 4; im++) {
        #pragma unroll
        for (int in = 0; in < 8; in++) {
            const int mr = m0 + wm0 + im * 16 + (lane >> 2);
            const int nc = n0 + wn0 + in * 8 + ((lane & 3) << 1);
            const long long o0 = zc + (long long)mr * ldc + nc;
            const long long o1 = zc + (long long)(mr + 8) * ldc + nc;
            float v0 = acc[im][in][0];
            float v1 = acc[im][in][1];
            float v2 = acc[im][in][2];
            float v3 = acc[im][in][3];
            if (OMODE != 2 && bias) {
                float2 bb = *reinterpret_cast<const float2*>(&bias[nc]);
                v0 += bb.x; v1 += bb.y; v2 += bb.x; v3 += bb.y;
            }
            if (OMODE == 0) {
                float* cf = const_cast<float*>(cf_or_gpre);
                *reinterpret_cast<float2*>(&cf[o0]) = make_float2(v0, v1);
                *reinterpret_cast<float2*>(&cf[o1]) = make_float2(v2, v3);
            } else {
                if (OMODE == 2) {
                    float2 gA = *reinterpret_cast<const float2*>(&cf_or_gpre[o0]);
                    float2 gB = *reinterpret_cast<const float2*>(&cf_or_gpre[o1]);
                    v0 *= 1.0f / (1.0f + expf(-gA.x));
                    v1 *= 1.0f / (1.0f + expf(-gA.y));
                    v2 *= 1.0f / (1.0f + expf(-gB.x));
                    v3 *= 1.0f / (1.0f + expf(-gB.y));
                }
                __nv_bfloat16 h0, l0, h1, l1, h2, l2, h3, l3;
                split2(v0, h0, l0); split2(v1, h1, l1);
                split2(v2, h2, l2); split2(v3, h3, l3);
                *reinterpret_cast<__nv_bfloat162*>(&ch[o0]) = __nv_bfloat162(h0, h1);
                *reinterpret_cast<__nv_bfloat162*>(&ch[o1]) = __nv_bfloat162(h2, h3);
                *reinterpret_cast<__nv_bfloat162*>(&cl[o0]) = __nv_bfloat162(l0, l1);
                *reinterpret_cast<__nv_bfloat162*>(&cl[o1]) = __nv_bfloat162(l2, l3);
            }
        }
    }
}

// ===================== glue kernels =====================
__global__ __launch_bounds__(256)
void split_kernel(const float* __restrict__ src,
                  __nv_bfloat16* __restrict__ hi, __nv_bfloat16* __restrict__ lo)
{
    const size_t i = ((size_t)blockIdx.x * 256 + threadIdx.x) * 4;
    float4 v = *reinterpret_cast<const float4*>(src + i);
    __nv_bfloat16 h0,l0,h1,l1,h2,l2,h3,l3;
    split2(v.x, h0, l0); split2(v.y, h1, l1); split2(v.z, h2, l2); split2(v.w, h3, l3);
    *reinterpret_cast<__nv_bfloat162*>(hi + i)     = __nv_bfloat162(h0, h1);
    *reinterpret_cast<__nv_bfloat162*>(hi + i + 2) = __nv_bfloat162(h2, h3);
    *reinterpret_cast<__nv_bfloat162*>(lo + i)     = __nv_bfloat162(l0, l1);
    *reinterpret_cast<__nv_bfloat162*>(lo + i + 2) = __nv_bfloat162(l2, l3);
}

// row softmax (len 2048) -> bf16 hi/lo pair
__global__ __launch_bounds__(256)
void softmax_split_kernel(const float* __restrict__ S,
                          __nv_bfloat16* __restrict__ ah, __nv_bfloat16* __restrict__ al)
{
    const size_t row = blockIdx.x;
    const float* p = S + row * SEQ;
    const int tid = threadIdx.x;
    __shared__ float red[8];

    float v[8];
    float mx = -1e30f;
    #pragma unroll
    for (int i = 0; i < 8; i++) { v[i] = p[i * 256 + tid]; mx = fmaxf(mx, v[i]); }
    #pragma unroll
    for (int o = 16; o; o >>= 1) mx = fmaxf(mx, __shfl_xor_sync(0xffffffffu, mx, o));
    if ((tid & 31) == 0) red[tid >> 5] = mx;
    __syncthreads();
    mx = red[0];
    #pragma unroll
    for (int i = 1; i < 8; i++) mx = fmaxf(mx, red[i]);
    __syncthreads();

    float s = 0.0f;
    #pragma unroll
    for (int i = 0; i < 8; i++) { v[i] = expf(v[i] - mx); s += v[i]; }
    #pragma unroll
    for (int o = 16; o; o >>= 1) s += __shfl_xor_sync(0xffffffffu, s, o);
    if ((tid & 31) == 0) red[tid >> 5] = s;
    __syncthreads();
    s = red[0];
    #pragma unroll
    for (int i = 1; i < 8; i++) s += red[i];

    const float inv = 1.0f / s;
    #pragma unroll
    for (int i = 0; i < 8; i++) {
        __nv_bfloat16 h, l;
        split2(v[i] * inv, h, l);
        ah[row * SEQ + i * 256 + tid] = h;
        al[row * SEQ + i * 256 + tid] = l;
    }
}

// ===================== host =====================
extern "C" void kernel_launch(void* const* d_in, const int* in_sizes, int n_in,
                              void* d_out, int out_size)
{
    (void)in_sizes; (void)n_in; (void)out_size;

    const float* queries = (const float*)d_in[0];
    const float* keys    = (const float*)d_in[1];
    const float* values  = (const float*)d_in[2];
    const float* Wq = (const float*)d_in[3];
    const float* bq = (const float*)d_in[4];
    const float* Wk = (const float*)d_in[5];
    const float* bk = (const float*)d_in[6];
    const float* Wv = (const float*)d_in[7];
    const float* bv = (const float*)d_in[8];
    const float* Wg = (const float*)d_in[9];
    const float* bg = (const float*)d_in[10];
    const float* Wo = (const float*)d_in[11];
    const float* bo = (const float*)d_in[12];
    float* out = (float*)d_out;

    void *Qh,*Ql,*Kh,*Kl,*Vh,*Vl,*qph,*qpl,*kph,*kpl,*vph,*vpl,*gch,*gcl,*ah,*al;
    void *scores,*gpre,*Wbase;
    cudaGetSymbolAddress(&Qh, g_Qh);   cudaGetSymbolAddress(&Ql, g_Ql);
    cudaGetSymbolAddress(&Kh, g_Kh);   cudaGetSymbolAddress(&Kl, g_Kl);
    cudaGetSymbolAddress(&Vh, g_Vh);   cudaGetSymbolAddress(&Vl, g_Vl);
    cudaGetSymbolAddress(&qph, g_qph); cudaGetSymbolAddress(&qpl, g_qpl);
    cudaGetSymbolAddress(&kph, g_kph); cudaGetSymbolAddress(&kpl, g_kpl);
    cudaGetSymbolAddress(&vph, g_vph); cudaGetSymbolAddress(&vpl, g_vpl);
    cudaGetSymbolAddress(&gch, g_gch); cudaGetSymbolAddress(&gcl, g_gcl);
    cudaGetSymbolAddress(&ah, g_ah);   cudaGetSymbolAddress(&al, g_al);
    cudaGetSymbolAddress(&scores, g_scores);
    cudaGetSymbolAddress(&gpre, g_gpre);
    cudaGetSymbolAddress(&Wbase, g_W);
    __nv_bfloat16* Wt = (__nv_bfloat16*)Wbase;   // 10 x DIM*DIM, layout [k][n]

    cudaFuncSetAttribute(hgemm<true,  0>, cudaFuncAttributeMaxDynamicSharedMemorySize, GEMM_SMEM);
    cudaFuncSetAttribute(hgemm<true,  1>, cudaFuncAttributeMaxDynamicSharedMemorySize, GEMM_SMEM);
    cudaFuncSetAttribute(hgemm<true,  2>, cudaFuncAttributeMaxDynamicSharedMemorySize, GEMM_SMEM);
    cudaFuncSetAttribute(hgemm<false, 0>, cudaFuncAttributeMaxDynamicSharedMemorySize, GEMM_SMEM);

    // ---- 1. split inputs and weights (weights stay [k][n], no transpose) ----
    {
        const unsigned nb = (unsigned)(NBF / 4 / 256);
        split_kernel<<<nb, 256>>>(queries, (__nv_bfloat16*)Qh, (__nv_bfloat16*)Ql);
        split_kernel<<<nb, 256>>>(keys,    (__nv_bfloat16*)Kh, (__nv_bfloat16*)Kl);
        split_kernel<<<nb, 256>>>(values,  (__nv_bfloat16*)Vh, (__nv_bfloat16*)Vl);
        const unsigned nw = (unsigned)((size_t)DIM * DIM / 4 / 256);
        split_kernel<<<nw, 256>>>(Wq, Wt + 0 * (size_t)DIM * DIM, Wt + 1 * (size_t)DIM * DIM);
        split_kernel<<<nw, 256>>>(Wk, Wt + 2 * (size_t)DIM * DIM, Wt + 3 * (size_t)DIM * DIM);
        split_kernel<<<nw, 256>>>(Wv, Wt + 4 * (size_t)DIM * DIM, Wt + 5 * (size_t)DIM * DIM);
        split_kernel<<<nw, 256>>>(Wg, Wt + 6 * (size_t)DIM * DIM, Wt + 7 * (size_t)DIM * DIM);
        split_kernel<<<nw, 256>>>(Wo, Wt + 8 * (size_t)DIM * DIM, Wt + 9 * (size_t)DIM * DIM);
    }

    // ---- 2. projections: X @ W + b   (B = W, [k][n] -> TRANSB=true) ----
    {
        dim3 g(DIM / 128, MTOT / 256, 1);
        hgemm<true, 1><<<g, 256, GEMM_SMEM>>>(
            (const __nv_bfloat16*)Qh, (const __nv_bfloat16*)Ql,
            Wt + 0 * (size_t)DIM * DIM, Wt + 1 * (size_t)DIM * DIM,
            nullptr, (__nv_bfloat16*)qph, (__nv_bfloat16*)qpl, bq,
            DIM, DIM, DIM, DIM, 0, 0, 0);
        hgemm<true, 1><<<g, 256, GEMM_SMEM>>>(
            (const __nv_bfloat16*)Kh, (const __nv_bfloat16*)Kl,
            Wt + 2 * (size_t)DIM * DIM, Wt + 3 * (size_t)DIM * DIM,
            nullptr, (__nv_bfloat16*)kph, (__nv_bfloat16*)kpl, bk,
            DIM, DIM, DIM, DIM, 0, 0, 0);
        hgemm<true, 1><<<g, 256, GEMM_SMEM>>>(
            (const __nv_bfloat16*)Vh, (const __nv_bfloat16*)Vl,
            Wt + 4 * (size_t)DIM * DIM, Wt + 5 * (size_t)DIM * DIM,
            nullptr, (__nv_bfloat16*)vph, (__nv_bfloat16*)vpl, bv,
            DIM, DIM, DIM, DIM, 0, 0, 0);
        hgemm<true, 0><<<g, 256, GEMM_SMEM>>>(
            (const __nv_bfloat16*)Qh, (const __nv_bfloat16*)Ql,
            Wt + 6 * (size_t)DIM * DIM, Wt + 7 * (size_t)DIM * DIM,
            (const float*)gpre, nullptr, nullptr, bg,
            DIM, DIM, DIM, DIM, 0, 0, 0);
    }

    // ---- 3. scores[b] = q[b] @ k[b]^T  (B = k, [n][k] -> TRANSB=false) ----
    {
        dim3 g(SEQ / 128, SEQ / 256, BATCH);
        hgemm<false, 0><<<g, 256, GEMM_SMEM>>>(
            (const __nv_bfloat16*)qph, (const __nv_bfloat16*)qpl,
            (const __nv_bfloat16*)kph, (const __nv_bfloat16*)kpl,
            (const float*)scores, nullptr, nullptr, nullptr,
            DIM, DIM, SEQ, DIM,
            (long long)SEQ * DIM, (long long)SEQ * DIM, (long long)SEQ * SEQ);
    }

    // ---- 4. softmax -> bf16 pair ----
    softmax_split_kernel<<<BATCH * SEQ, 256>>>((const float*)scores,
        (__nv_bfloat16*)ah, (__nv_bfloat16*)al);

    // ---- 5. gated ctx = (attn @ v) * sigmoid(gpre)  (fused gate, OMODE 2) ----
    {
        dim3 g(DIM / 128, SEQ / 256, BATCH);
        hgemm<true, 2><<<g, 256, GEMM_SMEM>>>(
            (const __nv_bfloat16*)ah, (const __nv_bfloat16*)al,
            (const __nv_bfloat16*)vph, (const __nv_bfloat16*)vpl,
            (const float*)gpre, (__nv_bfloat16*)gch, (__nv_bfloat16*)gcl, nullptr,
            SEQ, DIM, DIM, SEQ,
            (long long)SEQ * SEQ, (long long)SEQ * DIM, (long long)SEQ * DIM);
    }

    // ---- 6. out = gated @ Wo + bo ----
    {
        dim3 g(DIM / 128, MTOT / 256, 1);
        hgemm<true, 0><<<g, 256, GEMM_SMEM>>>(
            (const __nv_bfloat16*)gch, (const __nv_bfloat16*)gcl,
            Wt + 8 * (size_t)DIM * DIM, Wt + 9 * (size_t)DIM * DIM,
            (const float*)out, nullptr, nullptr, bo,
            DIM, DIM, DIM, DIM, 0, 0, 0);
    }
}

// round 7
// speedup vs baseline: 1.1792x; 1.1792x over previous
#include <cuda_runtime.h>
#include <cuda_bf16.h>
#include <math.h>
#include <stdint.h>

#define BATCH 8
#define SEQ   2048
#define DIM   1024
#define MTOT  (BATCH * SEQ)   // 16384

#define NBF ((size_t)MTOT * DIM)         // 16,777,216
#define NSC ((size_t)BATCH * SEQ * SEQ)  // 33,554,432

// ===================== scratch (no cudaMalloc allowed) =====================
__device__ __align__(1024) __nv_bfloat16 g_Qh[NBF], g_Ql[NBF];   // split inputs
__device__ __align__(1024) __nv_bfloat16 g_Kh[NBF], g_Kl[NBF];
__device__ __align__(1024) __nv_bfloat16 g_Vh[NBF], g_Vl[NBF];
__device__ __align__(1024) __nv_bfloat16 g_qph[NBF], g_qpl[NBF]; // q projection
__device__ __align__(1024) __nv_bfloat16 g_kph[NBF], g_kpl[NBF]; // k projection
__device__ __align__(1024) __nv_bfloat16 g_vph[NBF], g_vpl[NBF]; // v projection [s][d]
__device__ __align__(1024) __nv_bfloat16 g_gch[NBF], g_gcl[NBF]; // gated context
__device__ __align__(1024) __nv_bfloat16 g_ah[NSC], g_al[NSC];   // softmax(attn)
__device__ __align__(1024) __nv_bfloat16 g_W[10][DIM * DIM];     // W h/l x5, layout [k][n]
__device__ __align__(1024) float g_scores[NSC];
__device__ __align__(1024) float g_gpre[NBF];

// ===================== PTX wrappers (baseline sm_80+ features only) =========
__device__ __forceinline__ uint32_t smem_u32(const void* p) {
    uint32_t a;
    asm("{ .reg .u64 t; cvta.to.shared.u64 t, %1; cvt.u32.u64 %0, t; }" : "=r"(a) : "l"(p));
    return a;
}
__device__ __forceinline__ void cpa16(uint32_t dst, const void* src) {
    asm volatile("cp.async.cg.shared.global [%0], [%1], 16;" :: "r"(dst), "l"(src));
}
__device__ __forceinline__ void cp_commit() {
    asm volatile("cp.async.commit_group;" ::: "memory");
}
template <int N>
__device__ __forceinline__ void cp_wait() {
    asm volatile("cp.async.wait_group %0;" :: "n"(N) : "memory");
}
__device__ __forceinline__ void ldm4(uint32_t r[4], uint32_t addr) {
    asm volatile("ldmatrix.sync.aligned.m8n8.x4.shared.b16 {%0,%1,%2,%3}, [%4];"
                 : "=r"(r[0]), "=r"(r[1]), "=r"(r[2]), "=r"(r[3]) : "r"(addr));
}
__device__ __forceinline__ void ldm4t(uint32_t r[4], uint32_t addr) {
    asm volatile("ldmatrix.sync.aligned.m8n8.x4.trans.shared.b16 {%0,%1,%2,%3}, [%4];"
                 : "=r"(r[0]), "=r"(r[1]), "=r"(r[2]), "=r"(r[3]) : "r"(addr));
}
__device__ __forceinline__ void mma16816(float c[4],
                                         const uint32_t a[4],
                                         uint32_t b0, uint32_t b1) {
    asm volatile(
        "mma.sync.aligned.m16n8k16.row.col.f32.bf16.bf16.f32 "
        "{%0,%1,%2,%3}, {%4,%5,%6,%7}, {%8,%9}, {%0,%1,%2,%3};"
        : "+f"(c[0]), "+f"(c[1]), "+f"(c[2]), "+f"(c[3])
        : "r"(a[0]), "r"(a[1]), "r"(a[2]), "r"(a[3]), "r"(b0), "r"(b1));
}
__device__ __forceinline__ void split2(float x, __nv_bfloat16& h, __nv_bfloat16& l) {
    h = __float2bfloat16(x);
    l = __float2bfloat16(x - __bfloat162float(h));
}

// ===================== bf16x3 HMMA GEMM (R5 config + fused gate) ===========
// CTA tile 128x128, 128 threads / 4 warps, warp tile 64x64, double-buffered.
// D = A @ op(B), fp32 accumulate, 3 MMA passes (hh + hl + lh).
// TRANSB=false: B stored [n][k]. TRANSB=true: B stored [k][n].
// OMODE 0: fp32 out (+bias).
// OMODE 1: bf16 hi/lo pair out (+bias).
// OMODE 2: gated bf16 hi/lo out: val * sigmoid(gpre) (gpre passed via cf_or_gpre).
#define PA_E   40            // A / B-nontrans row pitch (elems): 32 data + 8 pad
#define PA_B   (PA_E * 2)    // 80 bytes
#define PBT_E  136           // B-trans row pitch (elems): 128 data + 8 pad
#define PBT_B  (PBT_E * 2)   // 272 bytes
#define MAT_BYTES   10240
#define STAGE_BYTES (4 * MAT_BYTES)           // Ah, Al, Bh, Bl
#define GEMM_SMEM   (2 * STAGE_BYTES)         // double buffered = 81920 B

template <bool TRANSB, int OMODE>
__global__ void __launch_bounds__(128, 2)
hgemm(const __nv_bfloat16* __restrict__ gAh, const __nv_bfloat16* __restrict__ gAl,
      const __nv_bfloat16* __restrict__ gBh, const __nv_bfloat16* __restrict__ gBl,
      const float* __restrict__ cf_or_gpre,
      __nv_bfloat16* __restrict__ ch, __nv_bfloat16* __restrict__ cl,
      const float* __restrict__ bias,
      int lda, int ldb, int ldc, int K,
      long long sa, long long sb, long long sc)
{
    extern __shared__ __align__(128) char smem[];
    const uint32_t sbase = smem_u32(smem);

    const int tid  = threadIdx.x;
    const int wid  = tid >> 5;
    const int lane = tid & 31;
    const int m0   = blockIdx.y * 128;
    const int n0   = blockIdx.x * 128;
    const int z    = blockIdx.z;

    gAh += (long long)z * sa;  gAl += (long long)z * sa;
    gBh += (long long)z * sb;  gBl += (long long)z * sb;

    const int wm0 = (wid >> 1) * 64;    // warp m offset
    const int wn0 = (wid & 1) * 64;     // warp n offset

    float acc[4][8][4];
    #pragma unroll
    for (int i = 0; i < 4; i++)
        #pragma unroll
        for (int j = 0; j < 8; j++)
            #pragma unroll
            for (int r = 0; r < 4; r++) acc[i][j][r] = 0.0f;

    const int nchunks = K >> 5;

    // ------- stage loader (128 threads) -------
    auto load_stage = [&](int s, int k0) {
        const uint32_t st = sbase + s * STAGE_BYTES;
        #pragma unroll
        for (int j = 0; j < 4; j++) {
            const int c = tid + 128 * j;
            {   // A hi/lo: 128 rows x 32 cols
                const int row = c >> 2, col = c & 3;
                const uint32_t so = st + row * PA_B + col * 16;
                const long long go = (long long)(m0 + row) * lda + k0 + col * 8;
                cpa16(so,             gAh + go);
                cpa16(so + MAT_BYTES, gAl + go);
            }
            if (TRANSB) {   // B: 32 rows (k) x 128 cols (n)
                const int row = c >> 4, col = c & 15;
                const uint32_t so = st + 2 * MAT_BYTES + row * PBT_B + col * 16;
                const long long go = (long long)(k0 + row) * ldb + n0 + col * 8;
                cpa16(so,             gBh + go);
                cpa16(so + MAT_BYTES, gBl + go);
            } else {        // B: 128 rows (n) x 32 cols (k)
                const int row = c >> 2, col = c & 3;
                const uint32_t so = st + 2 * MAT_BYTES + row * PA_B + col * 16;
                const long long go = (long long)(n0 + row) * ldb + k0 + col * 8;
                cpa16(so,             gBh + go);
                cpa16(so + MAT_BYTES, gBl + go);
            }
        }
    };

    // ------- compute one stage -------
    auto compute_stage = [&](int s) {
        const uint32_t ab = sbase + s * STAGE_BYTES;
        const uint32_t bb = ab + 2 * MAT_BYTES;
        #pragma unroll
        for (int ks = 0; ks < 32; ks += 16) {
            uint32_t ah[4][4], al[4][4];
            #pragma unroll
            for (int im = 0; im < 4; im++) {
                const uint32_t addr = ab
                    + (wm0 + im * 16 + (lane & 15)) * PA_B
                    + (ks + ((lane >> 4) << 3)) * 2;
                ldm4(ah[im], addr);
                ldm4(al[im], addr + MAT_BYTES);
            }
            #pragma unroll
            for (int half = 0; half < 4; half++) {   // n-tiles 2*half, 2*half+1
                const int nb = wn0 + half * 16;
                uint32_t rh[4], rl[4];
                if (TRANSB) {
                    const int krow = ks + (lane & 7) + (((lane >> 3) & 1) << 3);
                    const int ncol = nb + ((lane >> 4) << 3);
                    const uint32_t addr = bb + krow * PBT_B + ncol * 2;
                    ldm4t(rh, addr);
                    ldm4t(rl, addr + MAT_BYTES);
                } else {
                    const int nrow = nb + (lane & 7) + ((lane >> 4) << 3);
                    const int kcol = ks + (((lane >> 3) & 1) << 3);
                    const uint32_t addr = bb + nrow * PA_B + kcol * 2;
                    ldm4(rh, addr);
                    ldm4(rl, addr + MAT_BYTES);
                }
                #pragma unroll
                for (int im = 0; im < 4; im++) {
                    mma16816(acc[im][2*half],   ah[im], rh[0], rh[1]);
                    mma16816(acc[im][2*half],   ah[im], rl[0], rl[1]);
                    mma16816(acc[im][2*half],   al[im], rh[0], rh[1]);
                    mma16816(acc[im][2*half+1], ah[im], rh[2], rh[3]);
                    mma16816(acc[im][2*half+1], ah[im], rl[2], rl[3]);
                    mma16816(acc[im][2*half+1], al[im], rh[2], rh[3]);
                }
            }
        }
    };

    // ------- pipeline (double-buffered) -------
    load_stage(0, 0);
    cp_commit();
    for (int c = 0; c < nchunks; c++) {
        if (c + 1 < nchunks) {
            load_stage((c + 1) & 1, (c + 1) * 32);
            cp_commit();
            cp_wait<1>();
        } else {
            cp_wait<0>();
        }
        __syncthreads();
        compute_stage(c & 1);
        __syncthreads();
    }

    // ------- epilogue: write from fragments -------
    const long long zc = (long long)z * sc;
    #pragma unroll
    for (int im = 0; im < 4; im++) {
        #pragma unroll
        for (int in = 0; in < 8; in++) {
            const int mr = m0 + wm0 + im * 16 + (lane >> 2);
            const int nc = n0 + wn0 + in * 8 + ((lane & 3) << 1);
            const long long o0 = zc + (long long)mr * ldc + nc;
            const long long o1 = zc + (long long)(mr + 8) * ldc + nc;
            float v0 = acc[im][in][0];
            float v1 = acc[im][in][1];
            float v2 = acc[im][in][2];
            float v3 = acc[im][in][3];
            if (OMODE != 2 && bias) {
                float2 bb = *reinterpret_cast<const float2*>(&bias[nc]);
                v0 += bb.x; v1 += bb.y; v2 += bb.x; v3 += bb.y;
            }
            if (OMODE == 0) {
                float* cf = const_cast<float*>(cf_or_gpre);
                *reinterpret_cast<float2*>(&cf[o0]) = make_float2(v0, v1);
                *reinterpret_cast<float2*>(&cf[o1]) = make_float2(v2, v3);
            } else {
                if (OMODE == 2) {
                    float2 gA = *reinterpret_cast<const float2*>(&cf_or_gpre[o0]);
                    float2 gB = *reinterpret_cast<const float2*>(&cf_or_gpre[o1]);
                    v0 *= 1.0f / (1.0f + expf(-gA.x));
                    v1 *= 1.0f / (1.0f + expf(-gA.y));
                    v2 *= 1.0f / (1.0f + expf(-gB.x));
                    v3 *= 1.0f / (1.0f + expf(-gB.y));
                }
                __nv_bfloat16 h0, l0, h1, l1, h2, l2, h3, l3;
                split2(v0, h0, l0); split2(v1, h1, l1);
                split2(v2, h2, l2); split2(v3, h3, l3);
                *reinterpret_cast<__nv_bfloat162*>(&ch[o0]) = __nv_bfloat162(h0, h1);
                *reinterpret_cast<__nv_bfloat162*>(&ch[o1]) = __nv_bfloat162(h2, h3);
                *reinterpret_cast<__nv_bfloat162*>(&cl[o0]) = __nv_bfloat162(l0, l1);
                *reinterpret_cast<__nv_bfloat162*>(&cl[o1]) = __nv_bfloat162(l2, l3);
            }
        }
    }
}

// ===================== glue kernels =====================
__global__ __launch_bounds__(256)
void split_kernel(const float* __restrict__ src,
                  __nv_bfloat16* __restrict__ hi, __nv_bfloat16* __restrict__ lo)
{
    const size_t i = ((size_t)blockIdx.x * 256 + threadIdx.x) * 4;
    float4 v = *reinterpret_cast<const float4*>(src + i);
    __nv_bfloat16 h0,l0,h1,l1,h2,l2,h3,l3;
    split2(v.x, h0, l0); split2(v.y, h1, l1); split2(v.z, h2, l2); split2(v.w, h3, l3);
    *reinterpret_cast<__nv_bfloat162*>(hi + i)     = __nv_bfloat162(h0, h1);
    *reinterpret_cast<__nv_bfloat162*>(hi + i + 2) = __nv_bfloat162(h2, h3);
    *reinterpret_cast<__nv_bfloat162*>(lo + i)     = __nv_bfloat162(l0, l1);
    *reinterpret_cast<__nv_bfloat162*>(lo + i + 2) = __nv_bfloat162(l2, l3);
}

// row softmax (len 2048) -> bf16 hi/lo pair
__global__ __launch_bounds__(256)
void softmax_split_kernel(const float* __restrict__ S,
                          __nv_bfloat16* __restrict__ ah, __nv_bfloat16* __restrict__ al)
{
    const size_t row = blockIdx.x;
    const float* p = S + row * SEQ;
    const int tid = threadIdx.x;
    __shared__ float red[8];

    float v[8];
    float mx = -1e30f;
    #pragma unroll
    for (int i = 0; i < 8; i++) { v[i] = p[i * 256 + tid]; mx = fmaxf(mx, v[i]); }
    #pragma unroll
    for (int o = 16; o; o >>= 1) mx = fmaxf(mx, __shfl_xor_sync(0xffffffffu, mx, o));
    if ((tid & 31) == 0) red[tid >> 5] = mx;
    __syncthreads();
    mx = red[0];
    #pragma unroll
    for (int i = 1; i < 8; i++) mx = fmaxf(mx, red[i]);
    __syncthreads();

    float s = 0.0f;
    #pragma unroll
    for (int i = 0; i < 8; i++) { v[i] = expf(v[i] - mx); s += v[i]; }
    #pragma unroll
    for (int o = 16; o; o >>= 1) s += __shfl_xor_sync(0xffffffffu, s, o);
    if ((tid & 31) == 0) red[tid >> 5] = s;
    __syncthreads();
    s = red[0];
    #pragma unroll
    for (int i = 1; i < 8; i++) s += red[i];

    const float inv = 1.0f / s;
    #pragma unroll
    for (int i = 0; i < 8; i++) {
        __nv_bfloat16 h, l;
        split2(v[i] * inv, h, l);
        ah[row * SEQ + i * 256 + tid] = h;
        al[row * SEQ + i * 256 + tid] = l;
    }
}

// ===================== host =====================
extern "C" void kernel_launch(void* const* d_in, const int* in_sizes, int n_in,
                              void* d_out, int out_size)
{
    (void)in_sizes; (void)n_in; (void)out_size;

    const float* queries = (const float*)d_in[0];
    const float* keys    = (const float*)d_in[1];
    const float* values  = (const float*)d_in[2];
    const float* Wq = (const float*)d_in[3];
    const float* bq = (const float*)d_in[4];
    const float* Wk = (const float*)d_in[5];
    const float* bk = (const float*)d_in[6];
    const float* Wv = (const float*)d_in[7];
    const float* bv = (const float*)d_in[8];
    const float* Wg = (const float*)d_in[9];
    const float* bg = (const float*)d_in[10];
    const float* Wo = (const float*)d_in[11];
    const float* bo = (const float*)d_in[12];
    float* out = (float*)d_out;

    void *Qh,*Ql,*Kh,*Kl,*Vh,*Vl,*qph,*qpl,*kph,*kpl,*vph,*vpl,*gch,*gcl,*ah,*al;
    void *scores,*gpre,*Wbase;
    cudaGetSymbolAddress(&Qh, g_Qh);   cudaGetSymbolAddress(&Ql, g_Ql);
    cudaGetSymbolAddress(&Kh, g_Kh);   cudaGetSymbolAddress(&Kl, g_Kl);
    cudaGetSymbolAddress(&Vh, g_Vh);   cudaGetSymbolAddress(&Vl, g_Vl);
    cudaGetSymbolAddress(&qph, g_qph); cudaGetSymbolAddress(&qpl, g_qpl);
    cudaGetSymbolAddress(&kph, g_kph); cudaGetSymbolAddress(&kpl, g_kpl);
    cudaGetSymbolAddress(&vph, g_vph); cudaGetSymbolAddress(&vpl, g_vpl);
    cudaGetSymbolAddress(&gch, g_gch); cudaGetSymbolAddress(&gcl, g_gcl);
    cudaGetSymbolAddress(&ah, g_ah);   cudaGetSymbolAddress(&al, g_al);
    cudaGetSymbolAddress(&scores, g_scores);
    cudaGetSymbolAddress(&gpre, g_gpre);
    cudaGetSymbolAddress(&Wbase, g_W);
    __nv_bfloat16* Wt = (__nv_bfloat16*)Wbase;   // 10 x DIM*DIM, layout [k][n]

    cudaFuncSetAttribute(hgemm<true,  0>, cudaFuncAttributeMaxDynamicSharedMemorySize, GEMM_SMEM);
    cudaFuncSetAttribute(hgemm<true,  1>, cudaFuncAttributeMaxDynamicSharedMemorySize, GEMM_SMEM);
    cudaFuncSetAttribute(hgemm<true,  2>, cudaFuncAttributeMaxDynamicSharedMemorySize, GEMM_SMEM);
    cudaFuncSetAttribute(hgemm<false, 0>, cudaFuncAttributeMaxDynamicSharedMemorySize, GEMM_SMEM);

    // ---- 1. split inputs and weights (weights stay [k][n], no transpose) ----
    {
        const unsigned nb = (unsigned)(NBF / 4 / 256);
        split_kernel<<<nb, 256>>>(queries, (__nv_bfloat16*)Qh, (__nv_bfloat16*)Ql);
        split_kernel<<<nb, 256>>>(keys,    (__nv_bfloat16*)Kh, (__nv_bfloat16*)Kl);
        split_kernel<<<nb, 256>>>(values,  (__nv_bfloat16*)Vh, (__nv_bfloat16*)Vl);
        const unsigned nw = (unsigned)((size_t)DIM * DIM / 4 / 256);
        split_kernel<<<nw, 256>>>(Wq, Wt + 0 * (size_t)DIM * DIM, Wt + 1 * (size_t)DIM * DIM);
        split_kernel<<<nw, 256>>>(Wk, Wt + 2 * (size_t)DIM * DIM, Wt + 3 * (size_t)DIM * DIM);
        split_kernel<<<nw, 256>>>(Wv, Wt + 4 * (size_t)DIM * DIM, Wt + 5 * (size_t)DIM * DIM);
        split_kernel<<<nw, 256>>>(Wg, Wt + 6 * (size_t)DIM * DIM, Wt + 7 * (size_t)DIM * DIM);
        split_kernel<<<nw, 256>>>(Wo, Wt + 8 * (size_t)DIM * DIM, Wt + 9 * (size_t)DIM * DIM);
    }

    // ---- 2. projections: X @ W + b   (B = W, [k][n] -> TRANSB=true) ----
    {
        dim3 g(DIM / 128, MTOT / 128, 1);
        hgemm<true, 1><<<g, 128, GEMM_SMEM>>>(
            (const __nv_bfloat16*)Qh, (const __nv_bfloat16*)Ql,
            Wt + 0 * (size_t)DIM * DIM, Wt + 1 * (size_t)DIM * DIM,
            nullptr, (__nv_bfloat16*)qph, (__nv_bfloat16*)qpl, bq,
            DIM, DIM, DIM, DIM, 0, 0, 0);
        hgemm<true, 1><<<g, 128, GEMM_SMEM>>>(
            (const __nv_bfloat16*)Kh, (const __nv_bfloat16*)Kl,
            Wt + 2 * (size_t)DIM * DIM, Wt + 3 * (size_t)DIM * DIM,
            nullptr, (__nv_bfloat16*)kph, (__nv_bfloat16*)kpl, bk,
            DIM, DIM, DIM, DIM, 0, 0, 0);
        hgemm<true, 1><<<g, 128, GEMM_SMEM>>>(
            (const __nv_bfloat16*)Vh, (const __nv_bfloat16*)Vl,
            Wt + 4 * (size_t)DIM * DIM, Wt + 5 * (size_t)DIM * DIM,
            nullptr, (__nv_bfloat16*)vph, (__nv_bfloat16*)vpl, bv,
            DIM, DIM, DIM, DIM, 0, 0, 0);
        hgemm<true, 0><<<g, 128, GEMM_SMEM>>>(
            (const __nv_bfloat16*)Qh, (const __nv_bfloat16*)Ql,
            Wt + 6 * (size_t)DIM * DIM, Wt + 7 * (size_t)DIM * DIM,
            (const float*)gpre, nullptr, nullptr, bg,
            DIM, DIM, DIM, DIM, 0, 0, 0);
    }

    // ---- 3. scores[b] = q[b] @ k[b]^T  (B = k, [n][k] -> TRANSB=false) ----
    {
        dim3 g(SEQ / 128, SEQ / 128, BATCH);
        hgemm<false, 0><<<g, 128, GEMM_SMEM>>>(
            (const __nv_bfloat16*)qph, (const __nv_bfloat16*)qpl,
            (const __nv_bfloat16*)kph, (const __nv_bfloat16*)kpl,
            (const float*)scores, nullptr, nullptr, nullptr,
            DIM, DIM, SEQ, DIM,
            (long long)SEQ * DIM, (long long)SEQ * DIM, (long long)SEQ * SEQ);
    }

    // ---- 4. softmax -> bf16 pair ----
    softmax_split_kernel<<<BATCH * SEQ, 256>>>((const float*)scores,
        (__nv_bfloat16*)ah, (__nv_bfloat16*)al);

    // ---- 5. gated ctx = (attn @ v) * sigmoid(gpre)  (fused gate, OMODE 2) ----
    {
        dim3 g(DIM / 128, SEQ / 128, BATCH);
        hgemm<true, 2><<<g, 128, GEMM_SMEM>>>(
            (const __nv_bfloat16*)ah, (const __nv_bfloat16*)al,
            (const __nv_bfloat16*)vph, (const __nv_bfloat16*)vpl,
            (const float*)gpre, (__nv_bfloat16*)gch, (__nv_bfloat16*)gcl, nullptr,
            SEQ, DIM, DIM, SEQ,
            (long long)SEQ * SEQ, (long long)SEQ * DIM, (long long)SEQ * DIM);
    }

    // ---- 6. out = gated @ Wo + bo ----
    {
        dim3 g(DIM / 128, MTOT / 128, 1);
        hgemm<true, 0><<<g, 128, GEMM_SMEM>>>(
            (const __nv_bfloat16*)gch, (const __nv_bfloat16*)gcl,
            Wt + 8 * (size_t)DIM * DIM, Wt + 9 * (size_t)DIM * DIM,
            (const float*)out, nullptr, nullptr, bo,
            DIM, DIM, DIM, DIM, 0, 0, 0);
    }
}

// round 8
// speedup vs baseline: 1.1902x; 1.0093x over previous
#include <cuda_runtime.h>
#include <cuda_bf16.h>
#include <math.h>
#include <stdint.h>

#define BATCH 8
#define SEQ   2048
#define DIM   1024
#define MTOT  (BATCH * SEQ)   // 16384

#define NBF ((size_t)MTOT * DIM)         // 16,777,216
#define NSC ((size_t)BATCH * SEQ * SEQ)  // 33,554,432

// ===================== scratch (no cudaMalloc allowed) =====================
__device__ __align__(1024) __nv_bfloat16 g_Qh[NBF], g_Ql[NBF];   // split inputs
__device__ __align__(1024) __nv_bfloat16 g_Kh[NBF], g_Kl[NBF];
__device__ __align__(1024) __nv_bfloat16 g_Vh[NBF], g_Vl[NBF];
__device__ __align__(1024) __nv_bfloat16 g_qph[NBF], g_qpl[NBF]; // q projection
__device__ __align__(1024) __nv_bfloat16 g_kph[NBF], g_kpl[NBF]; // k projection
__device__ __align__(1024) __nv_bfloat16 g_vph[NBF], g_vpl[NBF]; // v projection [s][d]
__device__ __align__(1024) __nv_bfloat16 g_gch[NBF], g_gcl[NBF]; // gated context
__device__ __align__(1024) __nv_bfloat16 g_ah[NSC], g_al[NSC];   // softmax(attn)
__device__ __align__(1024) __nv_bfloat16 g_W[10][DIM * DIM];     // W h/l x5, layout [k][n]
__device__ __align__(1024) float g_scores[NSC];
__device__ __align__(1024) float g_gpre[NBF];
__device__ __align__(1024) float g_ctx[NBF];

// ===================== PTX wrappers (baseline sm_80+ features only) =========
__device__ __forceinline__ uint32_t smem_u32(const void* p) {
    uint32_t a;
    asm("{ .reg .u64 t; cvta.to.shared.u64 t, %1; cvt.u32.u64 %0, t; }" : "=r"(a) : "l"(p));
    return a;
}
__device__ __forceinline__ void cpa16(uint32_t dst, const void* src) {
    asm volatile("cp.async.cg.shared.global [%0], [%1], 16;" :: "r"(dst), "l"(src));
}
__device__ __forceinline__ void cp_commit() {
    asm volatile("cp.async.commit_group;" ::: "memory");
}
template <int N>
__device__ __forceinline__ void cp_wait() {
    asm volatile("cp.async.wait_group %0;" :: "n"(N) : "memory");
}
__device__ __forceinline__ void ldm4(uint32_t r[4], uint32_t addr) {
    asm volatile("ldmatrix.sync.aligned.m8n8.x4.shared.b16 {%0,%1,%2,%3}, [%4];"
                 : "=r"(r[0]), "=r"(r[1]), "=r"(r[2]), "=r"(r[3]) : "r"(addr));
}
__device__ __forceinline__ void ldm4t(uint32_t r[4], uint32_t addr) {
    asm volatile("ldmatrix.sync.aligned.m8n8.x4.trans.shared.b16 {%0,%1,%2,%3}, [%4];"
                 : "=r"(r[0]), "=r"(r[1]), "=r"(r[2]), "=r"(r[3]) : "r"(addr));
}
__device__ __forceinline__ void mma16816(float c[4],
                                         const uint32_t a[4],
                                         uint32_t b0, uint32_t b1) {
    asm volatile(
        "mma.sync.aligned.m16n8k16.row.col.f32.bf16.bf16.f32 "
        "{%0,%1,%2,%3}, {%4,%5,%6,%7}, {%8,%9}, {%0,%1,%2,%3};"
        : "+f"(c[0]), "+f"(c[1]), "+f"(c[2]), "+f"(c[3])
        : "r"(a[0]), "r"(a[1]), "r"(a[2]), "r"(a[3]), "r"(b0), "r"(b1));
}
__device__ __forceinline__ void split2(float x, __nv_bfloat16& h, __nv_bfloat16& l) {
    h = __float2bfloat16(x);
    l = __float2bfloat16(x - __bfloat162float(h));
}

// ===================== bf16x3 HMMA GEMM =====================
// CTA tile 128x128, 128 threads / 4 warps, warp tile 64x64, double-buffered,
// ONE __syncthreads per K-chunk (wait -> sync -> issue next load -> compute).
// D = A @ op(B), fp32 accumulate, 3 MMA passes (hh + hl + lh).
// TRANSB=false: B stored [n][k]. TRANSB=true: B stored [k][n].
// OMODE 0: fp32 out (+bias). OMODE 1: bf16 hi/lo pair out (+bias).
#define PA_E   40            // A / B-nontrans row pitch (elems): 32 data + 8 pad
#define PA_B   (PA_E * 2)    // 80 bytes
#define PBT_E  136           // B-trans row pitch (elems): 128 data + 8 pad
#define PBT_B  (PBT_E * 2)   // 272 bytes
#define MAT_BYTES   10240
#define STAGE_BYTES (4 * MAT_BYTES)           // Ah, Al, Bh, Bl
#define GEMM_SMEM   (2 * STAGE_BYTES)         // double buffered = 81920 B

template <bool TRANSB, int OMODE>
__global__ void __launch_bounds__(128, 2)
hgemm(const __nv_bfloat16* __restrict__ gAh, const __nv_bfloat16* __restrict__ gAl,
      const __nv_bfloat16* __restrict__ gBh, const __nv_bfloat16* __restrict__ gBl,
      float* __restrict__ cf,
      __nv_bfloat16* __restrict__ ch, __nv_bfloat16* __restrict__ cl,
      const float* __restrict__ bias,
      int lda, int ldb, int ldc, int K,
      long long sa, long long sb, long long sc)
{
    extern __shared__ __align__(128) char smem[];
    const uint32_t sbase = smem_u32(smem);

    const int tid  = threadIdx.x;
    const int wid  = tid >> 5;
    const int lane = tid & 31;
    const int m0   = blockIdx.y * 128;
    const int n0   = blockIdx.x * 128;
    const int z    = blockIdx.z;

    gAh += (long long)z * sa;  gAl += (long long)z * sa;
    gBh += (long long)z * sb;  gBl += (long long)z * sb;

    const int wm0 = (wid >> 1) * 64;    // warp m offset
    const int wn0 = (wid & 1) * 64;     // warp n offset

    float acc[4][8][4];
    #pragma unroll
    for (int i = 0; i < 4; i++)
        #pragma unroll
        for (int j = 0; j < 8; j++)
            #pragma unroll
            for (int r = 0; r < 4; r++) acc[i][j][r] = 0.0f;

    const int nchunks = K >> 5;

    // ------- stage loader (128 threads) -------
    auto load_stage = [&](int s, int k0) {
        const uint32_t st = sbase + s * STAGE_BYTES;
        #pragma unroll
        for (int j = 0; j < 4; j++) {
            const int c = tid + 128 * j;
            {   // A hi/lo: 128 rows x 32 cols
                const int row = c >> 2, col = c & 3;
                const uint32_t so = st + row * PA_B + col * 16;
                const long long go = (long long)(m0 + row) * lda + k0 + col * 8;
                cpa16(so,             gAh + go);
                cpa16(so + MAT_BYTES, gAl + go);
            }
            if (TRANSB) {   // B: 32 rows (k) x 128 cols (n)
                const int row = c >> 4, col = c & 15;
                const uint32_t so = st + 2 * MAT_BYTES + row * PBT_B + col * 16;
                const long long go = (long long)(k0 + row) * ldb + n0 + col * 8;
                cpa16(so,             gBh + go);
                cpa16(so + MAT_BYTES, gBl + go);
            } else {        // B: 128 rows (n) x 32 cols (k)
                const int row = c >> 2, col = c & 3;
                const uint32_t so = st + 2 * MAT_BYTES + row * PA_B + col * 16;
                const long long go = (long long)(n0 + row) * ldb + k0 + col * 8;
                cpa16(so,             gBh + go);
                cpa16(so + MAT_BYTES, gBl + go);
            }
        }
    };

    // ------- compute one stage -------
    auto compute_stage = [&](int s) {
        const uint32_t ab = sbase + s * STAGE_BYTES;
        const uint32_t bb = ab + 2 * MAT_BYTES;
        #pragma unroll
        for (int ks = 0; ks < 32; ks += 16) {
            uint32_t ah[4][4], al[4][4];
            #pragma unroll
            for (int im = 0; im < 4; im++) {
                const uint32_t addr = ab
                    + (wm0 + im * 16 + (lane & 15)) * PA_B
                    + (ks + ((lane >> 4) << 3)) * 2;
                ldm4(ah[im], addr);
                ldm4(al[im], addr + MAT_BYTES);
            }
            #pragma unroll
            for (int half = 0; half < 4; half++) {   // n-tiles 2*half, 2*half+1
                const int nb = wn0 + half * 16;
                uint32_t rh[4], rl[4];
                if (TRANSB) {
                    const int krow = ks + (lane & 7) + (((lane >> 3) & 1) << 3);
                    const int ncol = nb + ((lane >> 4) << 3);
                    const uint32_t addr = bb + krow * PBT_B + ncol * 2;
                    ldm4t(rh, addr);
                    ldm4t(rl, addr + MAT_BYTES);
                } else {
                    const int nrow = nb + (lane & 7) + ((lane >> 4) << 3);
                    const int kcol = ks + (((lane >> 3) & 1) << 3);
                    const uint32_t addr = bb + nrow * PA_B + kcol * 2;
                    ldm4(rh, addr);
                    ldm4(rl, addr + MAT_BYTES);
                }
                #pragma unroll
                for (int im = 0; im < 4; im++) {
                    mma16816(acc[im][2*half],   ah[im], rh[0], rh[1]);
                    mma16816(acc[im][2*half],   ah[im], rl[0], rl[1]);
                    mma16816(acc[im][2*half],   al[im], rh[0], rh[1]);
                    mma16816(acc[im][2*half+1], ah[im], rh[2], rh[3]);
                    mma16816(acc[im][2*half+1], ah[im], rl[2], rl[3]);
                    mma16816(acc[im][2*half+1], al[im], rh[2], rh[3]);
                }
            }
        }
    };

    // ------- pipeline: double-buffered, ONE sync per chunk -------
    // At iter c: outstanding = load(c). wait<0> -> all data for c in smem.
    // The same sync also proves every warp finished compute(c-1), so issuing
    // load(c+1) into buffer (c+1)&1 (== buffer of c-1) afterwards is safe.
    load_stage(0, 0);
    cp_commit();
    for (int c = 0; c < nchunks; c++) {
        cp_wait<0>();
        __syncthreads();
        if (c + 1 < nchunks) { load_stage((c + 1) & 1, (c + 1) * 32); cp_commit(); }
        compute_stage(c & 1);
    }

    // ------- epilogue: write from fragments -------
    const long long zc = (long long)z * sc;
    #pragma unroll
    for (int im = 0; im < 4; im++) {
        #pragma unroll
        for (int in = 0; in < 8; in++) {
            const int mr = m0 + wm0 + im * 16 + (lane >> 2);
            const int nc = n0 + wn0 + in * 8 + ((lane & 3) << 1);
            float bx = 0.0f, by = 0.0f;
            if (bias) { float2 bb = *reinterpret_cast<const float2*>(&bias[nc]); bx = bb.x; by = bb.y; }
            const float v0 = acc[im][in][0] + bx;
            const float v1 = acc[im][in][1] + by;
            const float v2 = acc[im][in][2] + bx;
            const float v3 = acc[im][in][3] + by;
            const long long o0 = zc + (long long)mr * ldc + nc;
            const long long o1 = zc + (long long)(mr + 8) * ldc + nc;
            if (OMODE == 0) {
                *reinterpret_cast<float2*>(&cf[o0]) = make_float2(v0, v1);
                *reinterpret_cast<float2*>(&cf[o1]) = make_float2(v2, v3);
            } else {
                __nv_bfloat16 h0, l0, h1, l1, h2, l2, h3, l3;
                split2(v0, h0, l0); split2(v1, h1, l1);
                split2(v2, h2, l2); split2(v3, h3, l3);
                *reinterpret_cast<__nv_bfloat162*>(&ch[o0]) = __nv_bfloat162(h0, h1);
                *reinterpret_cast<__nv_bfloat162*>(&ch[o1]) = __nv_bfloat162(h2, h3);
                *reinterpret_cast<__nv_bfloat162*>(&cl[o0]) = __nv_bfloat162(l0, l1);
                *reinterpret_cast<__nv_bfloat162*>(&cl[o1]) = __nv_bfloat162(l2, l3);
            }
        }
    }
}

// ===================== glue kernels =====================
__global__ __launch_bounds__(256)
void split_kernel(const float* __restrict__ src,
                  __nv_bfloat16* __restrict__ hi, __nv_bfloat16* __restrict__ lo)
{
    const size_t i = ((size_t)blockIdx.x * 256 + threadIdx.x) * 4;
    float4 v = *reinterpret_cast<const float4*>(src + i);
    __nv_bfloat16 h0,l0,h1,l1,h2,l2,h3,l3;
    split2(v.x, h0, l0); split2(v.y, h1, l1); split2(v.z, h2, l2); split2(v.w, h3, l3);
    *reinterpret_cast<__nv_bfloat162*>(hi + i)     = __nv_bfloat162(h0, h1);
    *reinterpret_cast<__nv_bfloat162*>(hi + i + 2) = __nv_bfloat162(h2, h3);
    *reinterpret_cast<__nv_bfloat162*>(lo + i)     = __nv_bfloat162(l0, l1);
    *reinterpret_cast<__nv_bfloat162*>(lo + i + 2) = __nv_bfloat162(l2, l3);
}

// row softmax (len 2048) -> bf16 hi/lo pair, float4 I/O
__global__ __launch_bounds__(256)
void softmax_split_kernel(const float* __restrict__ S,
                          __nv_bfloat16* __restrict__ ah, __nv_bfloat16* __restrict__ al)
{
    const size_t row = blockIdx.x;
    const float4* p4 = reinterpret_cast<const float4*>(S + row * SEQ);
    const int tid = threadIdx.x;
    __shared__ float red[8];

    float4 v[2];
    float mx = -1e30f;
    #pragma unroll
    for (int i = 0; i < 2; i++) {
        v[i] = p4[i * 256 + tid];
        mx = fmaxf(mx, fmaxf(fmaxf(v[i].x, v[i].y), fmaxf(v[i].z, v[i].w)));
    }
    #pragma unroll
    for (int o = 16; o; o >>= 1) mx = fmaxf(mx, __shfl_xor_sync(0xffffffffu, mx, o));
    if ((tid & 31) == 0) red[tid >> 5] = mx;
    __syncthreads();
    mx = red[0];
    #pragma unroll
    for (int i = 1; i < 8; i++) mx = fmaxf(mx, red[i]);
    __syncthreads();

    float s = 0.0f;
    #pragma unroll
    for (int i = 0; i < 2; i++) {
        v[i].x = expf(v[i].x - mx); v[i].y = expf(v[i].y - mx);
        v[i].z = expf(v[i].z - mx); v[i].w = expf(v[i].w - mx);
        s += v[i].x + v[i].y + v[i].z + v[i].w;
    }
    #pragma unroll
    for (int o = 16; o; o >>= 1) s += __shfl_xor_sync(0xffffffffu, s, o);
    if ((tid & 31) == 0) red[tid >> 5] = s;
    __syncthreads();
    s = red[0];
    #pragma unroll
    for (int i = 1; i < 8; i++) s += red[i];

    const float inv = 1.0f / s;
    #pragma unroll
    for (int i = 0; i < 2; i++) {
        const size_t e = row * SEQ + ((size_t)i * 256 + tid) * 4;
        __nv_bfloat16 h0,l0,h1,l1,h2,l2,h3,l3;
        split2(v[i].x * inv, h0, l0); split2(v[i].y * inv, h1, l1);
        split2(v[i].z * inv, h2, l2); split2(v[i].w * inv, h3, l3);
        *reinterpret_cast<__nv_bfloat162*>(ah + e)     = __nv_bfloat162(h0, h1);
        *reinterpret_cast<__nv_bfloat162*>(ah + e + 2) = __nv_bfloat162(h2, h3);
        *reinterpret_cast<__nv_bfloat162*>(al + e)     = __nv_bfloat162(l0, l1);
        *reinterpret_cast<__nv_bfloat162*>(al + e + 2) = __nv_bfloat162(l2, l3);
    }
}

// gated = ctx * sigmoid(gpre) -> bf16 hi/lo pair (coalesced float4)
__global__ __launch_bounds__(256)
void gate_split_kernel(const float* __restrict__ ctx, const float* __restrict__ gp,
                       __nv_bfloat16* __restrict__ gh, __nv_bfloat16* __restrict__ gl)
{
    const size_t i = ((size_t)blockIdx.x * 256 + threadIdx.x) * 4;
    float4 c = *reinterpret_cast<const float4*>(ctx + i);
    float4 g = *reinterpret_cast<const float4*>(gp + i);
    float o0 = c.x / (1.0f + expf(-g.x));
    float o1 = c.y / (1.0f + expf(-g.y));
    float o2 = c.z / (1.0f + expf(-g.z));
    float o3 = c.w / (1.0f + expf(-g.w));
    __nv_bfloat16 h0,l0,h1,l1,h2,l2,h3,l3;
    split2(o0, h0, l0); split2(o1, h1, l1); split2(o2, h2, l2); split2(o3, h3, l3);
    *reinterpret_cast<__nv_bfloat162*>(gh + i)     = __nv_bfloat162(h0, h1);
    *reinterpret_cast<__nv_bfloat162*>(gh + i + 2) = __nv_bfloat162(h2, h3);
    *reinterpret_cast<__nv_bfloat162*>(gl + i)     = __nv_bfloat162(l0, l1);
    *reinterpret_cast<__nv_bfloat162*>(gl + i + 2) = __nv_bfloat162(l2, l3);
}

// ===================== host =====================
extern "C" void kernel_launch(void* const* d_in, const int* in_sizes, int n_in,
                              void* d_out, int out_size)
{
    (void)in_sizes; (void)n_in; (void)out_size;

    const float* queries = (const float*)d_in[0];
    const float* keys    = (const float*)d_in[1];
    const float* values  = (const float*)d_in[2];
    const float* Wq = (const float*)d_in[3];
    const float* bq = (const float*)d_in[4];
    const float* Wk = (const float*)d_in[5];
    const float* bk = (const float*)d_in[6];
    const float* Wv = (const float*)d_in[7];
    const float* bv = (const float*)d_in[8];
    const float* Wg = (const float*)d_in[9];
    const float* bg = (const float*)d_in[10];
    const float* Wo = (const float*)d_in[11];
    const float* bo = (const float*)d_in[12];
    float* out = (float*)d_out;

    void *Qh,*Ql,*Kh,*Kl,*Vh,*Vl,*qph,*qpl,*kph,*kpl,*vph,*vpl,*gch,*gcl,*ah,*al;
    void *scores,*gpre,*ctx,*Wbase;
    cudaGetSymbolAddress(&Qh, g_Qh);   cudaGetSymbolAddress(&Ql, g_Ql);
    cudaGetSymbolAddress(&Kh, g_Kh);   cudaGetSymbolAddress(&Kl, g_Kl);
    cudaGetSymbolAddress(&Vh, g_Vh);   cudaGetSymbolAddress(&Vl, g_Vl);
    cudaGetSymbolAddress(&qph, g_qph); cudaGetSymbolAddress(&qpl, g_qpl);
    cudaGetSymbolAddress(&kph, g_kph); cudaGetSymbolAddress(&kpl, g_kpl);
    cudaGetSymbolAddress(&vph, g_vph); cudaGetSymbolAddress(&vpl, g_vpl);
    cudaGetSymbolAddress(&gch, g_gch); cudaGetSymbolAddress(&gcl, g_gcl);
    cudaGetSymbolAddress(&ah, g_ah);   cudaGetSymbolAddress(&al, g_al);
    cudaGetSymbolAddress(&scores, g_scores);
    cudaGetSymbolAddress(&gpre, g_gpre);
    cudaGetSymbolAddress(&ctx, g_ctx);
    cudaGetSymbolAddress(&Wbase, g_W);
    __nv_bfloat16* Wt = (__nv_bfloat16*)Wbase;   // 10 x DIM*DIM, layout [k][n]

    cudaFuncSetAttribute(hgemm<true,  0>, cudaFuncAttributeMaxDynamicSharedMemorySize, GEMM_SMEM);
    cudaFuncSetAttribute(hgemm<true,  1>, cudaFuncAttributeMaxDynamicSharedMemorySize, GEMM_SMEM);
    cudaFuncSetAttribute(hgemm<false, 0>, cudaFuncAttributeMaxDynamicSharedMemorySize, GEMM_SMEM);

    // ---- 1. split inputs and weights (weights stay [k][n], no transpose) ----
    {
        const unsigned nb = (unsigned)(NBF / 4 / 256);
        split_kernel<<<nb, 256>>>(queries, (__nv_bfloat16*)Qh, (__nv_bfloat16*)Ql);
        split_kernel<<<nb, 256>>>(keys,    (__nv_bfloat16*)Kh, (__nv_bfloat16*)Kl);
        split_kernel<<<nb, 256>>>(values,  (__nv_bfloat16*)Vh, (__nv_bfloat16*)Vl);
        const unsigned nw = (unsigned)((size_t)DIM * DIM / 4 / 256);
        split_kernel<<<nw, 256>>>(Wq, Wt + 0 * (size_t)DIM * DIM, Wt + 1 * (size_t)DIM * DIM);
        split_kernel<<<nw, 256>>>(Wk, Wt + 2 * (size_t)DIM * DIM, Wt + 3 * (size_t)DIM * DIM);
        split_kernel<<<nw, 256>>>(Wv, Wt + 4 * (size_t)DIM * DIM, Wt + 5 * (size_t)DIM * DIM);
        split_kernel<<<nw, 256>>>(Wg, Wt + 6 * (size_t)DIM * DIM, Wt + 7 * (size_t)DIM * DIM);
        split_kernel<<<nw, 256>>>(Wo, Wt + 8 * (size_t)DIM * DIM, Wt + 9 * (size_t)DIM * DIM);
    }

    // ---- 2. projections: X @ W + b   (B = W, [k][n] -> TRANSB=true) ----
    {
        dim3 g(DIM / 128, MTOT / 128, 1);
        hgemm<true, 1><<<g, 128, GEMM_SMEM>>>(
            (const __nv_bfloat16*)Qh, (const __nv_bfloat16*)Ql,
            Wt + 0 * (size_t)DIM * DIM, Wt + 1 * (size_t)DIM * DIM,
            nullptr, (__nv_bfloat16*)qph, (__nv_bfloat16*)qpl, bq,
            DIM, DIM, DIM, DIM, 0, 0, 0);
        hgemm<true, 1><<<g, 128, GEMM_SMEM>>>(
            (const __nv_bfloat16*)Kh, (const __nv_bfloat16*)Kl,
            Wt + 2 * (size_t)DIM * DIM, Wt + 3 * (size_t)DIM * DIM,
            nullptr, (__nv_bfloat16*)kph, (__nv_bfloat16*)kpl, bk,
            DIM, DIM, DIM, DIM, 0, 0, 0);
        hgemm<true, 1><<<g, 128, GEMM_SMEM>>>(
            (const __nv_bfloat16*)Vh, (const __nv_bfloat16*)Vl,
            Wt + 4 * (size_t)DIM * DIM, Wt + 5 * (size_t)DIM * DIM,
            nullptr, (__nv_bfloat16*)vph, (__nv_bfloat16*)vpl, bv,
            DIM, DIM, DIM, DIM, 0, 0, 0);
        hgemm<true, 0><<<g, 128, GEMM_SMEM>>>(
            (const __nv_bfloat16*)Qh, (const __nv_bfloat16*)Ql,
            Wt + 6 * (size_t)DIM * DIM, Wt + 7 * (size_t)DIM * DIM,
            (float*)gpre, nullptr, nullptr, bg,
            DIM, DIM, DIM, DIM, 0, 0, 0);
    }

    // ---- 3. scores[b] = q[b] @ k[b]^T  (B = k, [n][k] -> TRANSB=false) ----
    {
        dim3 g(SEQ / 128, SEQ / 128, BATCH);
        hgemm<false, 0><<<g, 128, GEMM_SMEM>>>(
            (const __nv_bfloat16*)qph, (const __nv_bfloat16*)qpl,
            (const __nv_bfloat16*)kph, (const __nv_bfloat16*)kpl,
            (float*)scores, nullptr, nullptr, nullptr,
            DIM, DIM, SEQ, DIM,
            (long long)SEQ * DIM, (long long)SEQ * DIM, (long long)SEQ * SEQ);
    }

    // ---- 4. softmax -> bf16 pair ----
    softmax_split_kernel<<<BATCH * SEQ, 256>>>((const float*)scores,
        (__nv_bfloat16*)ah, (__nv_bfloat16*)al);

    // ---- 5. context[b] = attn[b] @ v[b]  (B = v, [k][n] -> TRANSB=true) ----
    {
        dim3 g(DIM / 128, SEQ / 128, BATCH);
        hgemm<true, 0><<<g, 128, GEMM_SMEM>>>(
            (const __nv_bfloat16*)ah, (const __nv_bfloat16*)al,
            (const __nv_bfloat16*)vph, (const __nv_bfloat16*)vpl,
            (float*)ctx, nullptr, nullptr, nullptr,
            SEQ, DIM, DIM, SEQ,
            (long long)SEQ * SEQ, (long long)SEQ * DIM, (long long)SEQ * DIM);
    }

    // ---- 6. gate ----
    gate_split_kernel<<<(unsigned)(NBF / 4 / 256), 256>>>(
        (const float*)ctx, (const float*)gpre, (__nv_bfloat16*)gch, (__nv_bfloat16*)gcl);

    // ---- 7. out = gated @ Wo + bo ----
    {
        dim3 g(DIM / 128, MTOT / 128, 1);
        hgemm<true, 0><<<g, 128, GEMM_SMEM>>>(
            (const __nv_bfloat16*)gch, (const __nv_bfloat16*)gcl,
            Wt + 8 * (size_t)DIM * DIM, Wt + 9 * (size_t)DIM * DIM,
            out, nullptr, nullptr, bo,
            DIM, DIM, DIM, DIM, 0, 0, 0);
    }
}

// round 9
// speedup vs baseline: 1.3942x; 1.1714x over previous
#include <cuda_runtime.h>
#include <cuda_fp16.h>
#include <math.h>
#include <stdint.h>

#define BATCH 8
#define SEQ   2048
#define DIM   1024
#define MTOT  (BATCH * SEQ)   // 16384

#define NBF ((size_t)MTOT * DIM)         // 16,777,216
#define NSC ((size_t)BATCH * SEQ * SEQ)  // 33,554,432

// ===================== scratch (no cudaMalloc allowed) =====================
__device__ __align__(1024) __half g_Qh[NBF], g_Ql[NBF];   // queries split (pair)
__device__ __align__(1024) __half g_Kh[NBF], g_Kl[NBF];   // keys split (pair)
__device__ __align__(1024) __half g_Vh[NBF];              // values hi only
__device__ __align__(1024) __half g_qph[NBF], g_qpl[NBF]; // q projection (pair)
__device__ __align__(1024) __half g_kph[NBF], g_kpl[NBF]; // k projection (pair)
__device__ __align__(1024) __half g_vph[NBF], g_vpl[NBF]; // v projection (pair)
__device__ __align__(1024) __half g_gch[NBF];             // gated context hi only
__device__ __align__(1024) __half g_ah[NSC];              // softmax(attn) hi only
__device__ __align__(1024) __half g_W[10][DIM * DIM];     // W h/l x5, layout [k][n]
__device__ __align__(1024) float g_scores[NSC];
__device__ __align__(1024) float g_gpre[NBF];
__device__ __align__(1024) float g_ctx[NBF];

// ===================== PTX wrappers =====================
__device__ __forceinline__ uint32_t smem_u32(const void* p) {
    uint32_t a;
    asm("{ .reg .u64 t; cvta.to.shared.u64 t, %1; cvt.u32.u64 %0, t; }" : "=r"(a) : "l"(p));
    return a;
}
__device__ __forceinline__ void cpa16(uint32_t dst, const void* src) {
    asm volatile("cp.async.cg.shared.global [%0], [%1], 16;" :: "r"(dst), "l"(src));
}
__device__ __forceinline__ void cp_commit() {
    asm volatile("cp.async.commit_group;" ::: "memory");
}
template <int N>
__device__ __forceinline__ void cp_wait() {
    asm volatile("cp.async.wait_group %0;" :: "n"(N) : "memory");
}
__device__ __forceinline__ void ldm4(uint32_t r[4], uint32_t addr) {
    asm volatile("ldmatrix.sync.aligned.m8n8.x4.shared.b16 {%0,%1,%2,%3}, [%4];"
                 : "=r"(r[0]), "=r"(r[1]), "=r"(r[2]), "=r"(r[3]) : "r"(addr));
}
__device__ __forceinline__ void ldm4t(uint32_t r[4], uint32_t addr) {
    asm volatile("ldmatrix.sync.aligned.m8n8.x4.trans.shared.b16 {%0,%1,%2,%3}, [%4];"
                 : "=r"(r[0]), "=r"(r[1]), "=r"(r[2]), "=r"(r[3]) : "r"(addr));
}
__device__ __forceinline__ void mma16816(float c[4],
                                         const uint32_t a[4],
                                         uint32_t b0, uint32_t b1) {
    asm volatile(
        "mma.sync.aligned.m16n8k16.row.col.f32.f16.f16.f32 "
        "{%0,%1,%2,%3}, {%4,%5,%6,%7}, {%8,%9}, {%0,%1,%2,%3};"
        : "+f"(c[0]), "+f"(c[1]), "+f"(c[2]), "+f"(c[3])
        : "r"(a[0]), "r"(a[1]), "r"(a[2]), "r"(a[3]), "r"(b0), "r"(b1));
}
__device__ __forceinline__ void split2h(float x, __half& h, __half& l) {
    h = __float2half_rn(x);
    l = __float2half_rn(x - __half2float(h));
}

// ===================== fp16 split HMMA GEMM =====================
// CTA tile 128x128, 128 threads / 4 warps, warp tile 64x64, double-buffered,
// one __syncthreads per 32-K chunk.
// NPASS=3: D = (Ah+Al) @ op(Bh+Bl) minus Al*Bl  (loads Ah, Al, Bh, Bl)
// NPASS=2: D = Ah @ op(Bh+Bl)                    (loads Ah, Bh, Bl only)
// TRANSB=false: B stored [n][k]. TRANSB=true: B stored [k][n].
// OMODE 0: fp32 out (+bias). OMODE 1: fp16 hi/lo pair out (+bias).
#define PA_E   40            // A / B-nontrans row pitch (elems): 32 data + 8 pad
#define PA_B   (PA_E * 2)    // 80 bytes
#define PBT_E  136           // B-trans row pitch (elems): 128 data + 8 pad
#define PBT_B  (PBT_E * 2)   // 272 bytes
#define MAT_BYTES   10240
#define STAGE_BYTES (4 * MAT_BYTES)           // Ah, Al, Bh, Bl slots
#define GEMM_SMEM   (2 * STAGE_BYTES)         // double buffered = 81920 B

template <bool TRANSB, int NPASS, int OMODE>
__global__ void __launch_bounds__(128, 2)
hgemm(const __half* __restrict__ gAh, const __half* __restrict__ gAl,
      const __half* __restrict__ gBh, const __half* __restrict__ gBl,
      float* __restrict__ cf,
      __half* __restrict__ ch, __half* __restrict__ cl,
      const float* __restrict__ bias,
      int lda, int ldb, int ldc, int K,
      long long sa, long long sb, long long sc)
{
    extern __shared__ __align__(128) char smem[];
    const uint32_t sbase = smem_u32(smem);

    const int tid  = threadIdx.x;
    const int wid  = tid >> 5;
    const int lane = tid & 31;
    const int m0   = blockIdx.y * 128;
    const int n0   = blockIdx.x * 128;
    const int z    = blockIdx.z;

    gAh += (long long)z * sa;
    if (NPASS == 3) gAl += (long long)z * sa;
    gBh += (long long)z * sb;  gBl += (long long)z * sb;

    const int wm0 = (wid >> 1) * 64;    // warp m offset
    const int wn0 = (wid & 1) * 64;     // warp n offset

    float acc[4][8][4];
    #pragma unroll
    for (int i = 0; i < 4; i++)
        #pragma unroll
        for (int j = 0; j < 8; j++)
            #pragma unroll
            for (int r = 0; r < 4; r++) acc[i][j][r] = 0.0f;

    const int nchunks = K >> 5;

    // ------- stage loader (128 threads) -------
    auto load_stage = [&](int s, int k0) {
        const uint32_t st = sbase + s * STAGE_BYTES;
        #pragma unroll
        for (int j = 0; j < 4; j++) {
            const int c = tid + 128 * j;
            {   // A: 128 rows x 32 cols (hi, and lo if NPASS==3)
                const int row = c >> 2, col = c & 3;
                const uint32_t so = st + row * PA_B + col * 16;
                const long long go = (long long)(m0 + row) * lda + k0 + col * 8;
                cpa16(so, gAh + go);
                if (NPASS == 3) cpa16(so + MAT_BYTES, gAl + go);
            }
            if (TRANSB) {   // B: 32 rows (k) x 128 cols (n)
                const int row = c >> 4, col = c & 15;
                const uint32_t so = st + 2 * MAT_BYTES + row * PBT_B + col * 16;
                const long long go = (long long)(k0 + row) * ldb + n0 + col * 8;
                cpa16(so,             gBh + go);
                cpa16(so + MAT_BYTES, gBl + go);
            } else {        // B: 128 rows (n) x 32 cols (k)
                const int row = c >> 2, col = c & 3;
                const uint32_t so = st + 2 * MAT_BYTES + row * PA_B + col * 16;
                const long long go = (long long)(n0 + row) * ldb + k0 + col * 8;
                cpa16(so,             gBh + go);
                cpa16(so + MAT_BYTES, gBl + go);
            }
        }
    };

    // ------- compute one stage -------
    auto compute_stage = [&](int s) {
        const uint32_t ab = sbase + s * STAGE_BYTES;
        const uint32_t bb = ab + 2 * MAT_BYTES;
        #pragma unroll
        for (int ks = 0; ks < 32; ks += 16) {
            uint32_t ah[4][4], al[4][4];
            #pragma unroll
            for (int im = 0; im < 4; im++) {
                const uint32_t addr = ab
                    + (wm0 + im * 16 + (lane & 15)) * PA_B
                    + (ks + ((lane >> 4) << 3)) * 2;
                ldm4(ah[im], addr);
                if (NPASS == 3) ldm4(al[im], addr + MAT_BYTES);
            }
            #pragma unroll
            for (int half = 0; half < 4; half++) {   // n-tiles 2*half, 2*half+1
                const int nb = wn0 + half * 16;
                uint32_t rh[4], rl[4];
                if (TRANSB) {
                    const int krow = ks + (lane & 7) + (((lane >> 3) & 1) << 3);
                    const int ncol = nb + ((lane >> 4) << 3);
                    const uint32_t addr = bb + krow * PBT_B + ncol * 2;
                    ldm4t(rh, addr);
                    ldm4t(rl, addr + MAT_BYTES);
                } else {
                    const int nrow = nb + (lane & 7) + ((lane >> 4) << 3);
                    const int kcol = ks + (((lane >> 3) & 1) << 3);
                    const uint32_t addr = bb + nrow * PA_B + kcol * 2;
                    ldm4(rh, addr);
                    ldm4(rl, addr + MAT_BYTES);
                }
                #pragma unroll
                for (int im = 0; im < 4; im++) {
                    mma16816(acc[im][2*half],   ah[im], rh[0], rh[1]);
                    mma16816(acc[im][2*half],   ah[im], rl[0], rl[1]);
                    if (NPASS == 3) mma16816(acc[im][2*half], al[im], rh[0], rh[1]);
                    mma16816(acc[im][2*half+1], ah[im], rh[2], rh[3]);
                    mma16816(acc[im][2*half+1], ah[im], rl[2], rl[3]);
                    if (NPASS == 3) mma16816(acc[im][2*half+1], al[im], rh[2], rh[3]);
                }
            }
        }
    };

    // ------- pipeline: double-buffered, one sync per chunk -------
    load_stage(0, 0);
    cp_commit();
    for (int c = 0; c < nchunks; c++) {
        cp_wait<0>();
        __syncthreads();
        if (c + 1 < nchunks) { load_stage((c + 1) & 1, (c + 1) * 32); cp_commit(); }
        compute_stage(c & 1);
    }

    // ------- epilogue -------
    const long long zc = (long long)z * sc;
    #pragma unroll
    for (int im = 0; im < 4; im++) {
        #pragma unroll
        for (int in = 0; in < 8; in++) {
            const int mr = m0 + wm0 + im * 16 + (lane >> 2);
            const int nc = n0 + wn0 + in * 8 + ((lane & 3) << 1);
            float bx = 0.0f, by = 0.0f;
            if (bias) { float2 bb = *reinterpret_cast<const float2*>(&bias[nc]); bx = bb.x; by = bb.y; }
            const float v0 = acc[im][in][0] + bx;
            const float v1 = acc[im][in][1] + by;
            const float v2 = acc[im][in][2] + bx;
            const float v3 = acc[im][in][3] + by;
            const long long o0 = zc + (long long)mr * ldc + nc;
            const long long o1 = zc + (long long)(mr + 8) * ldc + nc;
            if (OMODE == 0) {
                *reinterpret_cast<float2*>(&cf[o0]) = make_float2(v0, v1);
                *reinterpret_cast<float2*>(&cf[o1]) = make_float2(v2, v3);
            } else {
                __half h0, l0, h1, l1, h2, l2, h3, l3;
                split2h(v0, h0, l0); split2h(v1, h1, l1);
                split2h(v2, h2, l2); split2h(v3, h3, l3);
                *reinterpret_cast<__half2*>(&ch[o0]) = __halves2half2(h0, h1);
                *reinterpret_cast<__half2*>(&ch[o1]) = __halves2half2(h2, h3);
                *reinterpret_cast<__half2*>(&cl[o0]) = __halves2half2(l0, l1);
                *reinterpret_cast<__half2*>(&cl[o1]) = __halves2half2(l2, l3);
            }
        }
    }
}

// ===================== glue kernels =====================
__global__ __launch_bounds__(256)
void split_kernel(const float* __restrict__ src,
                  __half* __restrict__ hi, __half* __restrict__ lo)
{
    const size_t i = ((size_t)blockIdx.x * 256 + threadIdx.x) * 4;
    float4 v = *reinterpret_cast<const float4*>(src + i);
    __half h0,l0,h1,l1,h2,l2,h3,l3;
    split2h(v.x, h0, l0); split2h(v.y, h1, l1); split2h(v.z, h2, l2); split2h(v.w, h3, l3);
    *reinterpret_cast<__half2*>(hi + i)     = __halves2half2(h0, h1);
    *reinterpret_cast<__half2*>(hi + i + 2) = __halves2half2(h2, h3);
    *reinterpret_cast<__half2*>(lo + i)     = __halves2half2(l0, l1);
    *reinterpret_cast<__half2*>(lo + i + 2) = __halves2half2(l2, l3);
}

// fp32 -> fp16 hi only
__global__ __launch_bounds__(256)
void conv_hi_kernel(const float* __restrict__ src, __half* __restrict__ hi)
{
    const size_t i = ((size_t)blockIdx.x * 256 + threadIdx.x) * 4;
    float4 v = *reinterpret_cast<const float4*>(src + i);
    *reinterpret_cast<__half2*>(hi + i)     = __halves2half2(__float2half_rn(v.x), __float2half_rn(v.y));
    *reinterpret_cast<__half2*>(hi + i + 2) = __halves2half2(__float2half_rn(v.z), __float2half_rn(v.w));
}

// row softmax (len 2048) -> fp16 hi only
__global__ __launch_bounds__(256)
void softmax_h_kernel(const float* __restrict__ S, __half* __restrict__ ah)
{
    const size_t row = blockIdx.x;
    const float4* p4 = reinterpret_cast<const float4*>(S + row * SEQ);
    const int tid = threadIdx.x;
    __shared__ float red[8];

    float4 v[2];
    float mx = -1e30f;
    #pragma unroll
    for (int i = 0; i < 2; i++) {
        v[i] = p4[i * 256 + tid];
        mx = fmaxf(mx, fmaxf(fmaxf(v[i].x, v[i].y), fmaxf(v[i].z, v[i].w)));
    }
    #pragma unroll
    for (int o = 16; o; o >>= 1) mx = fmaxf(mx, __shfl_xor_sync(0xffffffffu, mx, o));
    if ((tid & 31) == 0) red[tid >> 5] = mx;
    __syncthreads();
    mx = red[0];
    #pragma unroll
    for (int i = 1; i < 8; i++) mx = fmaxf(mx, red[i]);
    __syncthreads();

    float s = 0.0f;
    #pragma unroll
    for (int i = 0; i < 2; i++) {
        v[i].x = expf(v[i].x - mx); v[i].y = expf(v[i].y - mx);
        v[i].z = expf(v[i].z - mx); v[i].w = expf(v[i].w - mx);
        s += v[i].x + v[i].y + v[i].z + v[i].w;
    }
    #pragma unroll
    for (int o = 16; o; o >>= 1) s += __shfl_xor_sync(0xffffffffu, s, o);
    if ((tid & 31) == 0) red[tid >> 5] = s;
    __syncthreads();
    s = red[0];
    #pragma unroll
    for (int i = 1; i < 8; i++) s += red[i];

    const float inv = 1.0f / s;
    #pragma unroll
    for (int i = 0; i < 2; i++) {
        const size_t e = row * SEQ + ((size_t)i * 256 + tid) * 4;
        *reinterpret_cast<__half2*>(ah + e) =
            __halves2half2(__float2half_rn(v[i].x * inv), __float2half_rn(v[i].y * inv));
        *reinterpret_cast<__half2*>(ah + e + 2) =
            __halves2half2(__float2half_rn(v[i].z * inv), __float2half_rn(v[i].w * inv));
    }
}

// gated = ctx * sigmoid(gpre) -> fp16 hi only
__global__ __launch_bounds__(256)
void gate_h_kernel(const float* __restrict__ ctx, const float* __restrict__ gp,
                   __half* __restrict__ gh)
{
    const size_t i = ((size_t)blockIdx.x * 256 + threadIdx.x) * 4;
    float4 c = *reinterpret_cast<const float4*>(ctx + i);
    float4 g = *reinterpret_cast<const float4*>(gp + i);
    float o0 = c.x / (1.0f + expf(-g.x));
    float o1 = c.y / (1.0f + expf(-g.y));
    float o2 = c.z / (1.0f + expf(-g.z));
    float o3 = c.w / (1.0f + expf(-g.w));
    *reinterpret_cast<__half2*>(gh + i)     = __halves2half2(__float2half_rn(o0), __float2half_rn(o1));
    *reinterpret_cast<__half2*>(gh + i + 2) = __halves2half2(__float2half_rn(o2), __float2half_rn(o3));
}

// ===================== host =====================
extern "C" void kernel_launch(void* const* d_in, const int* in_sizes, int n_in,
                              void* d_out, int out_size)
{
    (void)in_sizes; (void)n_in; (void)out_size;

    const float* queries = (const float*)d_in[0];
    const float* keys    = (const float*)d_in[1];
    const float* values  = (const float*)d_in[2];
    const float* Wq = (const float*)d_in[3];
    const float* bq = (const float*)d_in[4];
    const float* Wk = (const float*)d_in[5];
    const float* bk = (const float*)d_in[6];
    const float* Wv = (const float*)d_in[7];
    const float* bv = (const float*)d_in[8];
    const float* Wg = (const float*)d_in[9];
    const float* bg = (const float*)d_in[10];
    const float* Wo = (const float*)d_in[11];
    const float* bo = (const float*)d_in[12];
    float* out = (float*)d_out;

    void *Qh,*Ql,*Kh,*Kl,*Vh,*qph,*qpl,*kph,*kpl,*vph,*vpl,*gch,*ah;
    void *scores,*gpre,*ctx,*Wbase;
    cudaGetSymbolAddress(&Qh, g_Qh);   cudaGetSymbolAddress(&Ql, g_Ql);
    cudaGetSymbolAddress(&Kh, g_Kh);   cudaGetSymbolAddress(&Kl, g_Kl);
    cudaGetSymbolAddress(&Vh, g_Vh);
    cudaGetSymbolAddress(&qph, g_qph); cudaGetSymbolAddress(&qpl, g_qpl);
    cudaGetSymbolAddress(&kph, g_kph); cudaGetSymbolAddress(&kpl, g_kpl);
    cudaGetSymbolAddress(&vph, g_vph); cudaGetSymbolAddress(&vpl, g_vpl);
    cudaGetSymbolAddress(&gch, g_gch); cudaGetSymbolAddress(&ah, g_ah);
    cudaGetSymbolAddress(&scores, g_scores);
    cudaGetSymbolAddress(&gpre, g_gpre);
    cudaGetSymbolAddress(&ctx, g_ctx);
    cudaGetSymbolAddress(&Wbase, g_W);
    __half* Wt = (__half*)Wbase;   // 10 x DIM*DIM, layout [k][n]

    cudaFuncSetAttribute(hgemm<true,  3, 1>, cudaFuncAttributeMaxDynamicSharedMemorySize, GEMM_SMEM);
    cudaFuncSetAttribute(hgemm<false, 3, 0>, cudaFuncAttributeMaxDynamicSharedMemorySize, GEMM_SMEM);
    cudaFuncSetAttribute(hgemm<true,  2, 1>, cudaFuncAttributeMaxDynamicSharedMemorySize, GEMM_SMEM);
    cudaFuncSetAttribute(hgemm<true,  2, 0>, cudaFuncAttributeMaxDynamicSharedMemorySize, GEMM_SMEM);

    // ---- 1. split inputs and weights ----
    {
        const unsigned nb = (unsigned)(NBF / 4 / 256);
        split_kernel<<<nb, 256>>>(queries, (__half*)Qh, (__half*)Ql);
        split_kernel<<<nb, 256>>>(keys,    (__half*)Kh, (__half*)Kl);
        conv_hi_kernel<<<nb, 256>>>(values, (__half*)Vh);
        const unsigned nw = (unsigned)((size_t)DIM * DIM / 4 / 256);
        split_kernel<<<nw, 256>>>(Wq, Wt + 0 * (size_t)DIM * DIM, Wt + 1 * (size_t)DIM * DIM);
        split_kernel<<<nw, 256>>>(Wk, Wt + 2 * (size_t)DIM * DIM, Wt + 3 * (size_t)DIM * DIM);
        split_kernel<<<nw, 256>>>(Wv, Wt + 4 * (size_t)DIM * DIM, Wt + 5 * (size_t)DIM * DIM);
        split_kernel<<<nw, 256>>>(Wg, Wt + 6 * (size_t)DIM * DIM, Wt + 7 * (size_t)DIM * DIM);
        split_kernel<<<nw, 256>>>(Wo, Wt + 8 * (size_t)DIM * DIM, Wt + 9 * (size_t)DIM * DIM);
    }

    // ---- 2. projections: X @ W + b   (B = W, [k][n] -> TRANSB=true) ----
    {
        dim3 g(DIM / 128, MTOT / 128, 1);
        // Q, K: full 3-pass (feed the logit path)
        hgemm<true, 3, 1><<<g, 128, GEMM_SMEM>>>(
            (const __half*)Qh, (const __half*)Ql,
            Wt + 0 * (size_t)DIM * DIM, Wt + 1 * (size_t)DIM * DIM,
            nullptr, (__half*)qph, (__half*)qpl, bq,
            DIM, DIM, DIM, DIM, 0, 0, 0);
        hgemm<true, 3, 1><<<g, 128, GEMM_SMEM>>>(
            (const __half*)Kh, (const __half*)Kl,
            Wt + 2 * (size_t)DIM * DIM, Wt + 3 * (size_t)DIM * DIM,
            nullptr, (__half*)kph, (__half*)kpl, bk,
            DIM, DIM, DIM, DIM, 0, 0, 0);
        // V, G: 2-pass (A hi only)
        hgemm<true, 2, 1><<<g, 128, GEMM_SMEM>>>(
            (const __half*)Vh, nullptr,
            Wt + 4 * (size_t)DIM * DIM, Wt + 5 * (size_t)DIM * DIM,
            nullptr, (__half*)vph, (__half*)vpl, bv,
            DIM, DIM, DIM, DIM, 0, 0, 0);
        hgemm<true, 2, 0><<<g, 128, GEMM_SMEM>>>(
            (const __half*)Qh, nullptr,
            Wt + 6 * (size_t)DIM * DIM, Wt + 7 * (size_t)DIM * DIM,
            (float*)gpre, nullptr, nullptr, bg,
            DIM, DIM, DIM, DIM, 0, 0, 0);
    }

    // ---- 3. scores[b] = q[b] @ k[b]^T  (3-pass; B = k, [n][k] -> TRANSB=false) ----
    {
        dim3 g(SEQ / 128, SEQ / 128, BATCH);
        hgemm<false, 3, 0><<<g, 128, GEMM_SMEM>>>(
            (const __half*)qph, (const __half*)qpl,
            (const __half*)kph, (const __half*)kpl,
            (float*)scores, nullptr, nullptr, nullptr,
            DIM, DIM, SEQ, DIM,
            (long long)SEQ * DIM, (long long)SEQ * DIM, (long long)SEQ * SEQ);
    }

    // ---- 4. softmax -> fp16 hi only ----
    softmax_h_kernel<<<BATCH * SEQ, 256>>>((const float*)scores, (__half*)ah);

    // ---- 5. context[b] = attn[b] @ v[b]  (2-pass; B = v pair, [k][n]) ----
    {
        dim3 g(DIM / 128, SEQ / 128, BATCH);
        hgemm<true, 2, 0><<<g, 128, GEMM_SMEM>>>(
            (const __half*)ah, nullptr,
            (const __half*)vph, (const __half*)vpl,
            (float*)ctx, nullptr, nullptr, nullptr,
            SEQ, DIM, DIM, SEQ,
            (long long)SEQ * SEQ, (long long)SEQ * DIM, (long long)SEQ * DIM);
    }

    // ---- 6. gate -> fp16 hi only ----
    gate_h_kernel<<<(unsigned)(NBF / 4 / 256), 256>>>(
        (const float*)ctx, (const float*)gpre, (__half*)gch);

    // ---- 7. out = gated @ Wo + bo  (2-pass) ----
    {
        dim3 g(DIM / 128, MTOT / 128, 1);
        hgemm<true, 2, 0><<<g, 128, GEMM_SMEM>>>(
            (const __half*)gch, nullptr,
            Wt + 8 * (size_t)DIM * DIM, Wt + 9 * (size_t)DIM * DIM,
            out, nullptr, nullptr, bo,
            DIM, DIM, DIM, DIM, 0, 0, 0);
    }
}

// round 10
// speedup vs baseline: 1.6320x; 1.1706x over previous
#include <cuda_runtime.h>
#include <cuda_fp16.h>
#include <math.h>
#include <stdint.h>

#define BATCH 8
#define SEQ   2048
#define DIM   1024
#define MTOT  (BATCH * SEQ)   // 16384
#define DD    ((size_t)DIM * DIM)

#define NBF ((size_t)MTOT * DIM)         // 16,777,216
#define NSC ((size_t)BATCH * SEQ * SEQ)  // 33,554,432

// ===================== scratch (no cudaMalloc allowed) =====================
__device__ __align__(1024) __half g_inh[3 * NBF];   // hi: [0]=queries [1]=keys [2]=values
__device__ __align__(1024) __half g_inl[2 * NBF];   // lo: [0]=queries [1]=keys
__device__ __align__(1024) __half g_qkph[2 * NBF];  // [0]=q-proj hi, [1]=k-proj hi
__device__ __align__(1024) __half g_qkpl[2 * NBF];  // [0]=q-proj lo, [1]=k-proj lo
__device__ __align__(1024) __half g_vgh[2 * NBF];   // [0]=v-proj hi, [1]=gpre hi
__device__ __align__(1024) __half g_gch[NBF];       // gated context hi
__device__ __align__(1024) __half g_ah[NSC];        // softmax(attn) hi
__device__ __align__(1024) __half g_W[8 * DD];      // 0=Wqh 1=Wql 2=Wkh 3=Wkl 4=Wvh 5=Wgh 6=Woh 7=Wol
__device__ __align__(1024) float g_scores[NSC];
__device__ __align__(1024) float g_ctx[NBF];
__device__ __align__(1024) float g_bias[4 * DIM];   // 0=bq 1=bk 2=bv 3=bg

// ===================== PTX wrappers =====================
__device__ __forceinline__ uint32_t smem_u32(const void* p) {
    uint32_t a;
    asm("{ .reg .u64 t; cvta.to.shared.u64 t, %1; cvt.u32.u64 %0, t; }" : "=r"(a) : "l"(p));
    return a;
}
__device__ __forceinline__ void cpa16(uint32_t dst, const void* src) {
    asm volatile("cp.async.cg.shared.global [%0], [%1], 16;" :: "r"(dst), "l"(src));
}
__device__ __forceinline__ void cp_commit() {
    asm volatile("cp.async.commit_group;" ::: "memory");
}
template <int N>
__device__ __forceinline__ void cp_wait() {
    asm volatile("cp.async.wait_group %0;" :: "n"(N) : "memory");
}
__device__ __forceinline__ void ldm4(uint32_t r[4], uint32_t addr) {
    asm volatile("ldmatrix.sync.aligned.m8n8.x4.shared.b16 {%0,%1,%2,%3}, [%4];"
                 : "=r"(r[0]), "=r"(r[1]), "=r"(r[2]), "=r"(r[3]) : "r"(addr));
}
__device__ __forceinline__ void ldm4t(uint32_t r[4], uint32_t addr) {
    asm volatile("ldmatrix.sync.aligned.m8n8.x4.trans.shared.b16 {%0,%1,%2,%3}, [%4];"
                 : "=r"(r[0]), "=r"(r[1]), "=r"(r[2]), "=r"(r[3]) : "r"(addr));
}
__device__ __forceinline__ void mma16816(float c[4],
                                         const uint32_t a[4],
                                         uint32_t b0, uint32_t b1) {
    asm volatile(
        "mma.sync.aligned.m16n8k16.row.col.f32.f16.f16.f32 "
        "{%0,%1,%2,%3}, {%4,%5,%6,%7}, {%8,%9}, {%0,%1,%2,%3};"
        : "+f"(c[0]), "+f"(c[1]), "+f"(c[2]), "+f"(c[3])
        : "r"(a[0]), "r"(a[1]), "r"(a[2]), "r"(a[3]), "r"(b0), "r"(b1));
}
__device__ __forceinline__ void split2h(float x, __half& h, __half& l) {
    h = __float2half_rn(x);
    l = __float2half_rn(x - __half2float(h));
}

// ===================== fp16 split HMMA GEMM =====================
// CTA tile 128x128, 128 threads / 4 warps, warp tile 64x64, double-buffered,
// one __syncthreads per 32-K chunk.
// NPASS=3: Ah*Bh + Ah*Bl + Al*Bh   (loads Ah, Al, Bh, Bl)
// NPASS=2: Ah*Bh + Ah*Bl           (loads Ah, Bh, Bl)
// NPASS=1: Ah*Bh                   (loads Ah, Bh)
// TRANSB=false: B stored [n][k]. TRANSB=true: B stored [k][n].
// OMODE 0: fp32 out (+bias). OMODE 1: fp16 hi/lo pair (+bias). OMODE 2: fp16 hi (+bias).
// blockIdx.z strides all pointers (batch OR fused-problem select); bias += z*sbias.
#define PA_E   40
#define PA_B   (PA_E * 2)    // 80 bytes
#define PBT_E  136
#define PBT_B  (PBT_E * 2)   // 272 bytes
#define MAT_BYTES   10240
#define STAGE_BYTES (4 * MAT_BYTES)
#define GEMM_SMEM   (2 * STAGE_BYTES)         // 81920 B

template <bool TRANSB, int NPASS, int OMODE>
__global__ void __launch_bounds__(128, 2)
hgemm(const __half* __restrict__ gAh, const __half* __restrict__ gAl,
      const __half* __restrict__ gBh, const __half* __restrict__ gBl,
      float* __restrict__ cf,
      __half* __restrict__ ch, __half* __restrict__ cl,
      const float* __restrict__ bias,
      int lda, int ldb, int ldc, int K,
      long long sa, long long sb, long long sc, int sbias)
{
    extern __shared__ __align__(128) char smem[];
    const uint32_t sbase = smem_u32(smem);

    const int tid  = threadIdx.x;
    const int wid  = tid >> 5;
    const int lane = tid & 31;
    const int m0   = blockIdx.y * 128;
    const int n0   = blockIdx.x * 128;
    const int z    = blockIdx.z;

    gAh += (long long)z * sa;
    if (NPASS == 3) gAl += (long long)z * sa;
    gBh += (long long)z * sb;
    if (NPASS >= 2) gBl += (long long)z * sb;
    if (bias) bias += (long long)z * sbias;

    const int wm0 = (wid >> 1) * 64;
    const int wn0 = (wid & 1) * 64;

    float acc[4][8][4];
    #pragma unroll
    for (int i = 0; i < 4; i++)
        #pragma unroll
        for (int j = 0; j < 8; j++)
            #pragma unroll
            for (int r = 0; r < 4; r++) acc[i][j][r] = 0.0f;

    const int nchunks = K >> 5;

    // ------- stage loader (128 threads) -------
    auto load_stage = [&](int s, int k0) {
        const uint32_t st = sbase + s * STAGE_BYTES;
        #pragma unroll
        for (int j = 0; j < 4; j++) {
            const int c = tid + 128 * j;
            {   // A: 128 rows x 32 cols
                const int row = c >> 2, col = c & 3;
                const uint32_t so = st + row * PA_B + col * 16;
                const long long go = (long long)(m0 + row) * lda + k0 + col * 8;
                cpa16(so, gAh + go);
                if (NPASS == 3) cpa16(so + MAT_BYTES, gAl + go);
            }
            if (TRANSB) {   // B: 32 rows (k) x 128 cols (n)
                const int row = c >> 4, col = c & 15;
                const uint32_t so = st + 2 * MAT_BYTES + row * PBT_B + col * 16;
                const long long go = (long long)(k0 + row) * ldb + n0 + col * 8;
                cpa16(so, gBh + go);
                if (NPASS >= 2) cpa16(so + MAT_BYTES, gBl + go);
            } else {        // B: 128 rows (n) x 32 cols (k)
                const int row = c >> 2, col = c & 3;
                const uint32_t so = st + 2 * MAT_BYTES + row * PA_B + col * 16;
                const long long go = (long long)(n0 + row) * ldb + k0 + col * 8;
                cpa16(so, gBh + go);
                if (NPASS >= 2) cpa16(so + MAT_BYTES, gBl + go);
            }
        }
    };

    // ------- compute one stage -------
    auto compute_stage = [&](int s) {
        const uint32_t ab = sbase + s * STAGE_BYTES;
        const uint32_t bb = ab + 2 * MAT_BYTES;
        #pragma unroll
        for (int ks = 0; ks < 32; ks += 16) {
            uint32_t ah[4][4], al[4][4];
            #pragma unroll
            for (int im = 0; im < 4; im++) {
                const uint32_t addr = ab
                    + (wm0 + im * 16 + (lane & 15)) * PA_B
                    + (ks + ((lane >> 4) << 3)) * 2;
                ldm4(ah[im], addr);
                if (NPASS == 3) ldm4(al[im], addr + MAT_BYTES);
            }
            #pragma unroll
            for (int half = 0; half < 4; half++) {
                const int nb = wn0 + half * 16;
                uint32_t rh[4], rl[4];
                if (TRANSB) {
                    const int krow = ks + (lane & 7) + (((lane >> 3) & 1) << 3);
                    const int ncol = nb + ((lane >> 4) << 3);
                    const uint32_t addr = bb + krow * PBT_B + ncol * 2;
                    ldm4t(rh, addr);
                    if (NPASS >= 2) ldm4t(rl, addr + MAT_BYTES);
                } else {
                    const int nrow = nb + (lane & 7) + ((lane >> 4) << 3);
                    const int kcol = ks + (((lane >> 3) & 1) << 3);
                    const uint32_t addr = bb + nrow * PA_B + kcol * 2;
                    ldm4(rh, addr);
                    if (NPASS >= 2) ldm4(rl, addr + MAT_BYTES);
                }
                #pragma unroll
                for (int im = 0; im < 4; im++) {
                    mma16816(acc[im][2*half],   ah[im], rh[0], rh[1]);
                    if (NPASS >= 2) mma16816(acc[im][2*half], ah[im], rl[0], rl[1]);
                    if (NPASS == 3) mma16816(acc[im][2*half], al[im], rh[0], rh[1]);
                    mma16816(acc[im][2*half+1], ah[im], rh[2], rh[3]);
                    if (NPASS >= 2) mma16816(acc[im][2*half+1], ah[im], rl[2], rl[3]);
                    if (NPASS == 3) mma16816(acc[im][2*half+1], al[im], rh[2], rh[3]);
                }
            }
        }
    };

    // ------- pipeline: double-buffered, one sync per chunk -------
    load_stage(0, 0);
    cp_commit();
    for (int c = 0; c < nchunks; c++) {
        cp_wait<0>();
        __syncthreads();
        if (c + 1 < nchunks) { load_stage((c + 1) & 1, (c + 1) * 32); cp_commit(); }
        compute_stage(c & 1);
    }

    // ------- epilogue -------
    const long long zc = (long long)z * sc;
    #pragma unroll
    for (int im = 0; im < 4; im++) {
        #pragma unroll
        for (int in = 0; in < 8; in++) {
            const int mr = m0 + wm0 + im * 16 + (lane >> 2);
            const int nc = n0 + wn0 + in * 8 + ((lane & 3) << 1);
            float bx = 0.0f, by = 0.0f;
            if (bias) { float2 bb = *reinterpret_cast<const float2*>(&bias[nc]); bx = bb.x; by = bb.y; }
            const float v0 = acc[im][in][0] + bx;
            const float v1 = acc[im][in][1] + by;
            const float v2 = acc[im][in][2] + bx;
            const float v3 = acc[im][in][3] + by;
            const long long o0 = zc + (long long)mr * ldc + nc;
            const long long o1 = zc + (long long)(mr + 8) * ldc + nc;
            if (OMODE == 0) {
                *reinterpret_cast<float2*>(&cf[o0]) = make_float2(v0, v1);
                *reinterpret_cast<float2*>(&cf[o1]) = make_float2(v2, v3);
            } else if (OMODE == 2) {
                *reinterpret_cast<__half2*>(&ch[o0]) =
                    __halves2half2(__float2half_rn(v0), __float2half_rn(v1));
                *reinterpret_cast<__half2*>(&ch[o1]) =
                    __halves2half2(__float2half_rn(v2), __float2half_rn(v3));
            } else {
                __half h0, l0, h1, l1, h2, l2, h3, l3;
                split2h(v0, h0, l0); split2h(v1, h1, l1);
                split2h(v2, h2, l2); split2h(v3, h3, l3);
                *reinterpret_cast<__half2*>(&ch[o0]) = __halves2half2(h0, h1);
                *reinterpret_cast<__half2*>(&ch[o1]) = __halves2half2(h2, h3);
                *reinterpret_cast<__half2*>(&cl[o0]) = __halves2half2(l0, l1);
                *reinterpret_cast<__half2*>(&cl[o1]) = __halves2half2(l2, l3);
            }
        }
    }
}

// ===================== glue kernels =====================
__global__ __launch_bounds__(256)
void split_kernel(const float* __restrict__ src,
                  __half* __restrict__ hi, __half* __restrict__ lo)
{
    const size_t i = ((size_t)blockIdx.x * 256 + threadIdx.x) * 4;
    float4 v = *reinterpret_cast<const float4*>(src + i);
    __half h0,l0,h1,l1,h2,l2,h3,l3;
    split2h(v.x, h0, l0); split2h(v.y, h1, l1); split2h(v.z, h2, l2); split2h(v.w, h3, l3);
    *reinterpret_cast<__half2*>(hi + i)     = __halves2half2(h0, h1);
    *reinterpret_cast<__half2*>(hi + i + 2) = __halves2half2(h2, h3);
    *reinterpret_cast<__half2*>(lo + i)     = __halves2half2(l0, l1);
    *reinterpret_cast<__half2*>(lo + i + 2) = __halves2half2(l2, l3);
}

__global__ __launch_bounds__(256)
void conv_hi_kernel(const float* __restrict__ src, __half* __restrict__ hi)
{
    const size_t i = ((size_t)blockIdx.x * 256 + threadIdx.x) * 4;
    float4 v = *reinterpret_cast<const float4*>(src + i);
    *reinterpret_cast<__half2*>(hi + i)     = __halves2half2(__float2half_rn(v.x), __float2half_rn(v.y));
    *reinterpret_cast<__half2*>(hi + i + 2) = __halves2half2(__float2half_rn(v.z), __float2half_rn(v.w));
}

// copy 4 bias vectors into strided scratch
__global__ __launch_bounds__(256)
void gather_bias_kernel(const float* __restrict__ b0, const float* __restrict__ b1,
                        const float* __restrict__ b2, const float* __restrict__ b3,
                        float* __restrict__ out)
{
    const int v = blockIdx.x;
    const float* src = (v == 0) ? b0 : (v == 1) ? b1 : (v == 2) ? b2 : b3;
    for (int j = threadIdx.x; j < DIM; j += 256) out[(size_t)v * DIM + j] = src[j];
}

// row softmax (len 2048) -> fp16 hi
__global__ __launch_bounds__(256)
void softmax_h_kernel(const float* __restrict__ S, __half* __restrict__ ah)
{
    const size_t row = blockIdx.x;
    const float4* p4 = reinterpret_cast<const float4*>(S + row * SEQ);
    const int tid = threadIdx.x;
    __shared__ float red[8];

    float4 v[2];
    float mx = -1e30f;
    #pragma unroll
    for (int i = 0; i < 2; i++) {
        v[i] = p4[i * 256 + tid];
        mx = fmaxf(mx, fmaxf(fmaxf(v[i].x, v[i].y), fmaxf(v[i].z, v[i].w)));
    }
    #pragma unroll
    for (int o = 16; o; o >>= 1) mx = fmaxf(mx, __shfl_xor_sync(0xffffffffu, mx, o));
    if ((tid & 31) == 0) red[tid >> 5] = mx;
    __syncthreads();
    mx = red[0];
    #pragma unroll
    for (int i = 1; i < 8; i++) mx = fmaxf(mx, red[i]);
    __syncthreads();

    float s = 0.0f;
    #pragma unroll
    for (int i = 0; i < 2; i++) {
        v[i].x = expf(v[i].x - mx); v[i].y = expf(v[i].y - mx);
        v[i].z = expf(v[i].z - mx); v[i].w = expf(v[i].w - mx);
        s += v[i].x + v[i].y + v[i].z + v[i].w;
    }
    #pragma unroll
    for (int o = 16; o; o >>= 1) s += __shfl_xor_sync(0xffffffffu, s, o);
    if ((tid & 31) == 0) red[tid >> 5] = s;
    __syncthreads();
    s = red[0];
    #pragma unroll
    for (int i = 1; i < 8; i++) s += red[i];

    const float inv = 1.0f / s;
    #pragma unroll
    for (int i = 0; i < 2; i++) {
        const size_t e = row * SEQ + ((size_t)i * 256 + tid) * 4;
        *reinterpret_cast<__half2*>(ah + e) =
            __halves2half2(__float2half_rn(v[i].x * inv), __float2half_rn(v[i].y * inv));
        *reinterpret_cast<__half2*>(ah + e + 2) =
            __halves2half2(__float2half_rn(v[i].z * inv), __float2half_rn(v[i].w * inv));
    }
}

// gated = ctx * sigmoid(gpre_h) -> fp16 hi
__global__ __launch_bounds__(256)
void gate_h_kernel(const float* __restrict__ ctx, const __half* __restrict__ gp,
                   __half* __restrict__ gh)
{
    const size_t i = ((size_t)blockIdx.x * 256 + threadIdx.x) * 4;
    float4 c = *reinterpret_cast<const float4*>(ctx + i);
    __half2 g01 = *reinterpret_cast<const __half2*>(gp + i);
    __half2 g23 = *reinterpret_cast<const __half2*>(gp + i + 2);
    float o0 = c.x / (1.0f + expf(-__half2float(g01.x)));
    float o1 = c.y / (1.0f + expf(-__half2float(g01.y)));
    float o2 = c.z / (1.0f + expf(-__half2float(g23.x)));
    float o3 = c.w / (1.0f + expf(-__half2float(g23.y)));
    *reinterpret_cast<__half2*>(gh + i)     = __halves2half2(__float2half_rn(o0), __float2half_rn(o1));
    *reinterpret_cast<__half2*>(gh + i + 2) = __halves2half2(__float2half_rn(o2), __float2half_rn(o3));
}

// ===================== host =====================
extern "C" void kernel_launch(void* const* d_in, const int* in_sizes, int n_in,
                              void* d_out, int out_size)
{
    (void)in_sizes; (void)n_in; (void)out_size;

    const float* queries = (const float*)d_in[0];
    const float* keys    = (const float*)d_in[1];
    const float* values  = (const float*)d_in[2];
    const float* Wq = (const float*)d_in[3];
    const float* bq = (const float*)d_in[4];
    const float* Wk = (const float*)d_in[5];
    const float* bk = (const float*)d_in[6];
    const float* Wv = (const float*)d_in[7];
    const float* bv = (const float*)d_in[8];
    const float* Wg = (const float*)d_in[9];
    const float* bg = (const float*)d_in[10];
    const float* Wo = (const float*)d_in[11];
    const float* bo = (const float*)d_in[12];
    float* out = (float*)d_out;

    void *inh, *inl, *qkph, *qkpl, *vgh, *gch, *ah, *scores, *ctx, *Wbase, *biasb;
    cudaGetSymbolAddress(&inh, g_inh);   cudaGetSymbolAddress(&inl, g_inl);
    cudaGetSymbolAddress(&qkph, g_qkph); cudaGetSymbolAddress(&qkpl, g_qkpl);
    cudaGetSymbolAddress(&vgh, g_vgh);   cudaGetSymbolAddress(&gch, g_gch);
    cudaGetSymbolAddress(&ah, g_ah);     cudaGetSymbolAddress(&scores, g_scores);
    cudaGetSymbolAddress(&ctx, g_ctx);   cudaGetSymbolAddress(&Wbase, g_W);
    cudaGetSymbolAddress(&biasb, g_bias);
    __half* INH = (__half*)inh;  __half* INL = (__half*)inl;
    __half* QKH = (__half*)qkph; __half* QKL = (__half*)qkpl;
    __half* VGH = (__half*)vgh;
    __half* Wt  = (__half*)Wbase;
    float*  BIA = (float*)biasb;

    cudaFuncSetAttribute(hgemm<true,  3, 1>, cudaFuncAttributeMaxDynamicSharedMemorySize, GEMM_SMEM);
    cudaFuncSetAttribute(hgemm<true,  1, 2>, cudaFuncAttributeMaxDynamicSharedMemorySize, GEMM_SMEM);
    cudaFuncSetAttribute(hgemm<false, 3, 0>, cudaFuncAttributeMaxDynamicSharedMemorySize, GEMM_SMEM);
    cudaFuncSetAttribute(hgemm<true,  1, 0>, cudaFuncAttributeMaxDynamicSharedMemorySize, GEMM_SMEM);
    cudaFuncSetAttribute(hgemm<true,  2, 0>, cudaFuncAttributeMaxDynamicSharedMemorySize, GEMM_SMEM);

    // ---- 1. prep: splits + bias gather ----
    {
        const unsigned nb = (unsigned)(NBF / 4 / 256);
        split_kernel<<<nb, 256>>>(queries, INH,           INL);
        split_kernel<<<nb, 256>>>(keys,    INH + NBF,     INL + NBF);
        conv_hi_kernel<<<nb, 256>>>(values, INH + 2 * NBF);
        const unsigned nw = (unsigned)(DD / 4 / 256);
        split_kernel<<<nw, 256>>>(Wq, Wt + 0 * DD, Wt + 1 * DD);
        split_kernel<<<nw, 256>>>(Wk, Wt + 2 * DD, Wt + 3 * DD);
        conv_hi_kernel<<<nw, 256>>>(Wv, Wt + 4 * DD);
        conv_hi_kernel<<<nw, 256>>>(Wg, Wt + 5 * DD);
        split_kernel<<<nw, 256>>>(Wo, Wt + 6 * DD, Wt + 7 * DD);
        gather_bias_kernel<<<4, 256>>>(bq, bk, bv, bg, BIA);
    }

    // ---- 2a. fused Q+K projections (3-pass, pair out): z selects problem ----
    {
        dim3 g(DIM / 128, MTOT / 128, 2);
        hgemm<true, 3, 1><<<g, 128, GEMM_SMEM>>>(
            INH, INL,                         // A: queries / keys (stride NBF)
            Wt + 0 * DD, Wt + 1 * DD,         // B: Wq pair / Wk pair (stride 2*DD)
            nullptr, QKH, QKL, BIA,
            DIM, DIM, DIM, DIM,
            (long long)NBF, (long long)(2 * DD), (long long)NBF, DIM);
    }

    // ---- 2b. fused V+G projections (1-pass, hi out) ----
    {
        dim3 g(DIM / 128, MTOT / 128, 2);
        hgemm<true, 1, 2><<<g, 128, GEMM_SMEM>>>(
            INH + 2 * NBF, nullptr,           // z0: values (off +0), z1: queries (off -2*NBF)
            Wt + 4 * DD, nullptr,             // z0: Wvh, z1: Wgh (stride DD)
            nullptr, VGH, nullptr, BIA + 2 * DIM,
            DIM, DIM, DIM, DIM,
            -(long long)(2 * NBF), (long long)DD, (long long)NBF, DIM);
    }

    // ---- 3. scores[b] = q[b] @ k[b]^T (3-pass) ----
    {
        dim3 g(SEQ / 128, SEQ / 128, BATCH);
        hgemm<false, 3, 0><<<g, 128, GEMM_SMEM>>>(
            QKH, QKL,                         // q pair
            QKH + NBF, QKL + NBF,             // k pair
            (float*)scores, nullptr, nullptr, nullptr,
            DIM, DIM, SEQ, DIM,
            (long long)SEQ * DIM, (long long)SEQ * DIM, (long long)SEQ * SEQ, 0);
    }

    // ---- 4. softmax -> fp16 hi ----
    softmax_h_kernel<<<BATCH * SEQ, 256>>>((const float*)scores, (__half*)ah);

    // ---- 5. context[b] = attn[b] @ v[b] (1-pass) ----
    {
        dim3 g(DIM / 128, SEQ / 128, BATCH);
        hgemm<true, 1, 0><<<g, 128, GEMM_SMEM>>>(
            (const __half*)ah, nullptr,
            VGH, nullptr,                     // v-proj hi, [k][n]
            (float*)ctx, nullptr, nullptr, nullptr,
            SEQ, DIM, DIM, SEQ,
            (long long)SEQ * SEQ, (long long)SEQ * DIM, (long long)SEQ * DIM, 0);
    }

    // ---- 6. gate -> fp16 hi ----
    gate_h_kernel<<<(unsigned)(NBF / 4 / 256), 256>>>(
        (const float*)ctx, VGH + NBF, (__half*)gch);

    // ---- 7. out = gated @ Wo + bo (2-pass) ----
    {
        dim3 g(DIM / 128, MTOT / 128, 1);
        hgemm<true, 2, 0><<<g, 128, GEMM_SMEM>>>(
            (const __half*)gch, nullptr,
            Wt + 6 * DD, Wt + 7 * DD,
            out, nullptr, nullptr, bo,
            DIM, DIM, DIM, DIM, 0, 0, 0, 0);
    }
}

// round 11
// speedup vs baseline: 1.6874x; 1.0339x over previous
#include <cuda_runtime.h>
#include <cuda_fp16.h>
#include <math.h>
#include <stdint.h>

#define BATCH 8
#define SEQ   2048
#define DIM   1024
#define MTOT  (BATCH * SEQ)   // 16384
#define DD    ((size_t)DIM * DIM)

#define NBF ((size_t)MTOT * DIM)         // 16,777,216
#define NSC ((size_t)BATCH * SEQ * SEQ)  // 33,554,432

// ===================== scratch (no cudaMalloc allowed) =====================
__device__ __align__(1024) __half g_inh[3 * NBF];   // hi: [0]=queries [1]=keys [2]=values
__device__ __align__(1024) __half g_inl[2 * NBF];   // lo: [0]=queries [1]=keys
__device__ __align__(1024) __half g_qkph[2 * NBF];  // [0]=q-proj hi, [1]=k-proj hi
__device__ __align__(1024) __half g_qkpl[2 * NBF];  // [0]=q-proj lo, [1]=k-proj lo
__device__ __align__(1024) __half g_vgh[2 * NBF];   // [0]=v-proj hi, [1]=gpre hi
__device__ __align__(1024) __half g_gch[NBF];       // gated context hi
__device__ __align__(1024) __half g_ah[NSC];        // softmax(attn) hi
__device__ __align__(1024) __half g_W[7 * DD];      // 0=Wqh 1=Wql 2=Wkh 3=Wkl 4=Wvh 5=Wgh 6=Woh
__device__ __align__(1024) float g_scores[NSC];
__device__ __align__(1024) float g_bias[4 * DIM];   // 0=bq 1=bk 2=bv 3=bg

// ===================== PTX wrappers =====================
__device__ __forceinline__ uint32_t smem_u32(const void* p) {
    uint32_t a;
    asm("{ .reg .u64 t; cvta.to.shared.u64 t, %1; cvt.u32.u64 %0, t; }" : "=r"(a) : "l"(p));
    return a;
}
__device__ __forceinline__ void cpa16(uint32_t dst, const void* src) {
    asm volatile("cp.async.cg.shared.global [%0], [%1], 16;" :: "r"(dst), "l"(src));
}
__device__ __forceinline__ void cp_commit() {
    asm volatile("cp.async.commit_group;" ::: "memory");
}
template <int N>
__device__ __forceinline__ void cp_wait() {
    asm volatile("cp.async.wait_group %0;" :: "n"(N) : "memory");
}
__device__ __forceinline__ void ldm4(uint32_t r[4], uint32_t addr) {
    asm volatile("ldmatrix.sync.aligned.m8n8.x4.shared.b16 {%0,%1,%2,%3}, [%4];"
                 : "=r"(r[0]), "=r"(r[1]), "=r"(r[2]), "=r"(r[3]) : "r"(addr));
}
__device__ __forceinline__ void ldm4t(uint32_t r[4], uint32_t addr) {
    asm volatile("ldmatrix.sync.aligned.m8n8.x4.trans.shared.b16 {%0,%1,%2,%3}, [%4];"
                 : "=r"(r[0]), "=r"(r[1]), "=r"(r[2]), "=r"(r[3]) : "r"(addr));
}
__device__ __forceinline__ void mma16816(float c[4],
                                         const uint32_t a[4],
                                         uint32_t b0, uint32_t b1) {
    asm volatile(
        "mma.sync.aligned.m16n8k16.row.col.f32.f16.f16.f32 "
        "{%0,%1,%2,%3}, {%4,%5,%6,%7}, {%8,%9}, {%0,%1,%2,%3};"
        : "+f"(c[0]), "+f"(c[1]), "+f"(c[2]), "+f"(c[3])
        : "r"(a[0]), "r"(a[1]), "r"(a[2]), "r"(a[3]), "r"(b0), "r"(b1));
}
__device__ __forceinline__ void split2h(float x, __half& h, __half& l) {
    h = __float2half_rn(x);
    l = __float2half_rn(x - __half2float(h));
}
__device__ __forceinline__ float sigmoidf_(float x) {
    return 1.0f / (1.0f + expf(-x));
}

// ===================== fp16 split HMMA GEMM =====================
// CTA tile 128x128, 128 threads / 4 warps, warp tile 64x64, double-buffered,
// one __syncthreads per 32-K chunk.
// NPASS=3: Ah*Bh + Ah*Bl + Al*Bh   (loads Ah, Al, Bh, Bl)
// NPASS=2: Ah*Bh + Ah*Bl           (loads Ah, Bh, Bl)
// NPASS=1: Ah*Bh                   (loads Ah, Bh)
// TRANSB=false: B stored [n][k]. TRANSB=true: B stored [k][n].
// OMODE 0: fp32 out (+bias). OMODE 1: fp16 hi/lo pair (+bias). OMODE 2: fp16 hi (+bias).
// OMODE 3: gated fp16 hi: val * sigmoid(gpre_h), gpre_h passed via cl (same layout as out).
// blockIdx.z strides all pointers; bias += z*sbias.
#define PA_E   40
#define PA_B   (PA_E * 2)    // 80 bytes
#define PBT_E  136
#define PBT_B  (PBT_E * 2)   // 272 bytes
#define MAT_BYTES   10240
#define STAGE_BYTES (4 * MAT_BYTES)
#define GEMM_SMEM   (2 * STAGE_BYTES)         // 81920 B

template <bool TRANSB, int NPASS, int OMODE>
__global__ void __launch_bounds__(128, 2)
hgemm(const __half* __restrict__ gAh, const __half* __restrict__ gAl,
      const __half* __restrict__ gBh, const __half* __restrict__ gBl,
      float* __restrict__ cf,
      __half* __restrict__ ch, __half* __restrict__ cl,
      const float* __restrict__ bias,
      int lda, int ldb, int ldc, int K,
      long long sa, long long sb, long long sc, int sbias)
{
    extern __shared__ __align__(128) char smem[];
    const uint32_t sbase = smem_u32(smem);

    const int tid  = threadIdx.x;
    const int wid  = tid >> 5;
    const int lane = tid & 31;
    const int m0   = blockIdx.y * 128;
    const int n0   = blockIdx.x * 128;
    const int z    = blockIdx.z;

    gAh += (long long)z * sa;
    if (NPASS == 3) gAl += (long long)z * sa;
    gBh += (long long)z * sb;
    if (NPASS >= 2) gBl += (long long)z * sb;
    if (bias) bias += (long long)z * sbias;

    const int wm0 = (wid >> 1) * 64;
    const int wn0 = (wid & 1) * 64;

    float acc[4][8][4];
    #pragma unroll
    for (int i = 0; i < 4; i++)
        #pragma unroll
        for (int j = 0; j < 8; j++)
            #pragma unroll
            for (int r = 0; r < 4; r++) acc[i][j][r] = 0.0f;

    const int nchunks = K >> 5;

    // ------- stage loader (128 threads) -------
    auto load_stage = [&](int s, int k0) {
        const uint32_t st = sbase + s * STAGE_BYTES;
        #pragma unroll
        for (int j = 0; j < 4; j++) {
            const int c = tid + 128 * j;
            {   // A: 128 rows x 32 cols
                const int row = c >> 2, col = c & 3;
                const uint32_t so = st + row * PA_B + col * 16;
                const long long go = (long long)(m0 + row) * lda + k0 + col * 8;
                cpa16(so, gAh + go);
                if (NPASS == 3) cpa16(so + MAT_BYTES, gAl + go);
            }
            if (TRANSB) {   // B: 32 rows (k) x 128 cols (n)
                const int row = c >> 4, col = c & 15;
                const uint32_t so = st + 2 * MAT_BYTES + row * PBT_B + col * 16;
                const long long go = (long long)(k0 + row) * ldb + n0 + col * 8;
                cpa16(so, gBh + go);
                if (NPASS >= 2) cpa16(so + MAT_BYTES, gBl + go);
            } else {        // B: 128 rows (n) x 32 cols (k)
                const int row = c >> 2, col = c & 3;
                const uint32_t so = st + 2 * MAT_BYTES + row * PA_B + col * 16;
                const long long go = (long long)(n0 + row) * ldb + k0 + col * 8;
                cpa16(so, gBh + go);
                if (NPASS >= 2) cpa16(so + MAT_BYTES, gBl + go);
            }
        }
    };

    // ------- compute one stage -------
    auto compute_stage = [&](int s) {
        const uint32_t ab = sbase + s * STAGE_BYTES;
        const uint32_t bb = ab + 2 * MAT_BYTES;
        #pragma unroll
        for (int ks = 0; ks < 32; ks += 16) {
            uint32_t ah[4][4], al[4][4];
            #pragma unroll
            for (int im = 0; im < 4; im++) {
                const uint32_t addr = ab
                    + (wm0 + im * 16 + (lane & 15)) * PA_B
                    + (ks + ((lane >> 4) << 3)) * 2;
                ldm4(ah[im], addr);
                if (NPASS == 3) ldm4(al[im], addr + MAT_BYTES);
            }
            #pragma unroll
            for (int half = 0; half < 4; half++) {
                const int nb = wn0 + half * 16;
                uint32_t rh[4], rl[4];
                if (TRANSB) {
                    const int krow = ks + (lane & 7) + (((lane >> 3) & 1) << 3);
                    const int ncol = nb + ((lane >> 4) << 3);
                    const uint32_t addr = bb + krow * PBT_B + ncol * 2;
                    ldm4t(rh, addr);
                    if (NPASS >= 2) ldm4t(rl, addr + MAT_BYTES);
                } else {
                    const int nrow = nb + (lane & 7) + ((lane >> 4) << 3);
                    const int kcol = ks + (((lane >> 3) & 1) << 3);
                    const uint32_t addr = bb + nrow * PA_B + kcol * 2;
                    ldm4(rh, addr);
                    if (NPASS >= 2) ldm4(rl, addr + MAT_BYTES);
                }
                #pragma unroll
                for (int im = 0; im < 4; im++) {
                    mma16816(acc[im][2*half],   ah[im], rh[0], rh[1]);
                    if (NPASS >= 2) mma16816(acc[im][2*half], ah[im], rl[0], rl[1]);
                    if (NPASS == 3) mma16816(acc[im][2*half], al[im], rh[0], rh[1]);
                    mma16816(acc[im][2*half+1], ah[im], rh[2], rh[3]);
                    if (NPASS >= 2) mma16816(acc[im][2*half+1], ah[im], rl[2], rl[3]);
                    if (NPASS == 3) mma16816(acc[im][2*half+1], al[im], rh[2], rh[3]);
                }
            }
        }
    };

    // ------- pipeline: double-buffered, one sync per chunk -------
    load_stage(0, 0);
    cp_commit();
    for (int c = 0; c < nchunks; c++) {
        cp_wait<0>();
        __syncthreads();
        if (c + 1 < nchunks) { load_stage((c + 1) & 1, (c + 1) * 32); cp_commit(); }
        compute_stage(c & 1);
    }

    // ------- epilogue -------
    const long long zc = (long long)z * sc;
    #pragma unroll
    for (int im = 0; im < 4; im++) {
        #pragma unroll
        for (int in = 0; in < 8; in++) {
            const int mr = m0 + wm0 + im * 16 + (lane >> 2);
            const int nc = n0 + wn0 + in * 8 + ((lane & 3) << 1);
            float bx = 0.0f, by = 0.0f;
            if (OMODE != 3 && bias) {
                float2 bb = *reinterpret_cast<const float2*>(&bias[nc]);
                bx = bb.x; by = bb.y;
            }
            float v0 = acc[im][in][0] + bx;
            float v1 = acc[im][in][1] + by;
            float v2 = acc[im][in][2] + bx;
            float v3 = acc[im][in][3] + by;
            const long long o0 = zc + (long long)mr * ldc + nc;
            const long long o1 = zc + (long long)(mr + 8) * ldc + nc;
            if (OMODE == 0) {
                *reinterpret_cast<float2*>(&cf[o0]) = make_float2(v0, v1);
                *reinterpret_cast<float2*>(&cf[o1]) = make_float2(v2, v3);
            } else if (OMODE == 2 || OMODE == 3) {
                if (OMODE == 3) {
                    __half2 g01 = *reinterpret_cast<const __half2*>(&cl[o0]);
                    __half2 g23 = *reinterpret_cast<const __half2*>(&cl[o1]);
                    v0 *= sigmoidf_(__half2float(g01.x));
                    v1 *= sigmoidf_(__half2float(g01.y));
                    v2 *= sigmoidf_(__half2float(g23.x));
                    v3 *= sigmoidf_(__half2float(g23.y));
                }
                *reinterpret_cast<__half2*>(&ch[o0]) =
                    __halves2half2(__float2half_rn(v0), __float2half_rn(v1));
                *reinterpret_cast<__half2*>(&ch[o1]) =
                    __halves2half2(__float2half_rn(v2), __float2half_rn(v3));
            } else {
                __half h0, l0, h1, l1, h2, l2, h3, l3;
                split2h(v0, h0, l0); split2h(v1, h1, l1);
                split2h(v2, h2, l2); split2h(v3, h3, l3);
                *reinterpret_cast<__half2*>(&ch[o0]) = __halves2half2(h0, h1);
                *reinterpret_cast<__half2*>(&ch[o1]) = __halves2half2(h2, h3);
                *reinterpret_cast<__half2*>(&cl[o0]) = __halves2half2(l0, l1);
                *reinterpret_cast<__half2*>(&cl[o1]) = __halves2half2(l2, l3);
            }
        }
    }
}

// ===================== glue kernels =====================
__global__ __launch_bounds__(256)
void split_kernel(const float* __restrict__ src,
                  __half* __restrict__ hi, __half* __restrict__ lo)
{
    const size_t i = ((size_t)blockIdx.x * 256 + threadIdx.x) * 4;
    float4 v = *reinterpret_cast<const float4*>(src + i);
    __half h0,l0,h1,l1,h2,l2,h3,l3;
    split2h(v.x, h0, l0); split2h(v.y, h1, l1); split2h(v.z, h2, l2); split2h(v.w, h3, l3);
    *reinterpret_cast<__half2*>(hi + i)     = __halves2half2(h0, h1);
    *reinterpret_cast<__half2*>(hi + i + 2) = __halves2half2(h2, h3);
    *reinterpret_cast<__half2*>(lo + i)     = __halves2half2(l0, l1);
    *reinterpret_cast<__half2*>(lo + i + 2) = __halves2half2(l2, l3);
}

__global__ __launch_bounds__(256)
void conv_hi_kernel(const float* __restrict__ src, __half* __restrict__ hi)
{
    const size_t i = ((size_t)blockIdx.x * 256 + threadIdx.x) * 4;
    float4 v = *reinterpret_cast<const float4*>(src + i);
    *reinterpret_cast<__half2*>(hi + i)     = __halves2half2(__float2half_rn(v.x), __float2half_rn(v.y));
    *reinterpret_cast<__half2*>(hi + i + 2) = __halves2half2(__float2half_rn(v.z), __float2half_rn(v.w));
}

// copy 4 bias vectors into strided scratch
__global__ __launch_bounds__(256)
void gather_bias_kernel(const float* __restrict__ b0, const float* __restrict__ b1,
                        const float* __restrict__ b2, const float* __restrict__ b3,
                        float* __restrict__ out)
{
    const int v = blockIdx.x;
    const float* src = (v == 0) ? b0 : (v == 1) ? b1 : (v == 2) ? b2 : b3;
    for (int j = threadIdx.x; j < DIM; j += 256) out[(size_t)v * DIM + j] = src[j];
}

// row softmax (len 2048) -> fp16 hi
__global__ __launch_bounds__(256)
void softmax_h_kernel(const float* __restrict__ S, __half* __restrict__ ah)
{
    const size_t row = blockIdx.x;
    const float4* p4 = reinterpret_cast<const float4*>(S + row * SEQ);
    const int tid = threadIdx.x;
    __shared__ float red[8];

    float4 v[2];
    float mx = -1e30f;
    #pragma unroll
    for (int i = 0; i < 2; i++) {
        v[i] = p4[i * 256 + tid];
        mx = fmaxf(mx, fmaxf(fmaxf(v[i].x, v[i].y), fmaxf(v[i].z, v[i].w)));
    }
    #pragma unroll
    for (int o = 16; o; o >>= 1) mx = fmaxf(mx, __shfl_xor_sync(0xffffffffu, mx, o));
    if ((tid & 31) == 0) red[tid >> 5] = mx;
    __syncthreads();
    mx = red[0];
    #pragma unroll
    for (int i = 1; i < 8; i++) mx = fmaxf(mx, red[i]);
    __syncthreads();

    float s = 0.0f;
    #pragma unroll
    for (int i = 0; i < 2; i++) {
        v[i].x = expf(v[i].x - mx); v[i].y = expf(v[i].y - mx);
        v[i].z = expf(v[i].z - mx); v[i].w = expf(v[i].w - mx);
        s += v[i].x + v[i].y + v[i].z + v[i].w;
    }
    #pragma unroll
    for (int o = 16; o; o >>= 1) s += __shfl_xor_sync(0xffffffffu, s, o);
    if ((tid & 31) == 0) red[tid >> 5] = s;
    __syncthreads();
    s = red[0];
    #pragma unroll
    for (int i = 1; i < 8; i++) s += red[i];

    const float inv = 1.0f / s;
    #pragma unroll
    for (int i = 0; i < 2; i++) {
        const size_t e = row * SEQ + ((size_t)i * 256 + tid) * 4;
        *reinterpret_cast<__half2*>(ah + e) =
            __halves2half2(__float2half_rn(v[i].x * inv), __float2half_rn(v[i].y * inv));
        *reinterpret_cast<__half2*>(ah + e + 2) =
            __halves2half2(__float2half_rn(v[i].z * inv), __float2half_rn(v[i].w * inv));
    }
}

// ===================== host =====================
extern "C" void kernel_launch(void* const* d_in, const int* in_sizes, int n_in,
                              void* d_out, int out_size)
{
    (void)in_sizes; (void)n_in; (void)out_size;

    const float* queries = (const float*)d_in[0];
    const float* keys    = (const float*)d_in[1];
    const float* values  = (const float*)d_in[2];
    const float* Wq = (const float*)d_in[3];
    const float* bq = (const float*)d_in[4];
    const float* Wk = (const float*)d_in[5];
    const float* bk = (const float*)d_in[6];
    const float* Wv = (const float*)d_in[7];
    const float* bv = (const float*)d_in[8];
    const float* Wg = (const float*)d_in[9];
    const float* bg = (const float*)d_in[10];
    const float* Wo = (const float*)d_in[11];
    const float* bo = (const float*)d_in[12];
    float* out = (float*)d_out;

    void *inh, *inl, *qkph, *qkpl, *vgh, *gch, *ah, *scores, *Wbase, *biasb;
    cudaGetSymbolAddress(&inh, g_inh);   cudaGetSymbolAddress(&inl, g_inl);
    cudaGetSymbolAddress(&qkph, g_qkph); cudaGetSymbolAddress(&qkpl, g_qkpl);
    cudaGetSymbolAddress(&vgh, g_vgh);   cudaGetSymbolAddress(&gch, g_gch);
    cudaGetSymbolAddress(&ah, g_ah);     cudaGetSymbolAddress(&scores, g_scores);
    cudaGetSymbolAddress(&Wbase, g_W);   cudaGetSymbolAddress(&biasb, g_bias);
    __half* INH = (__half*)inh;  __half* INL = (__half*)inl;
    __half* QKH = (__half*)qkph; __half* QKL = (__half*)qkpl;
    __half* VGH = (__half*)vgh;
    __half* Wt  = (__half*)Wbase;
    float*  BIA = (float*)biasb;

    cudaFuncSetAttribute(hgemm<true,  3, 1>, cudaFuncAttributeMaxDynamicSharedMemorySize, GEMM_SMEM);
    cudaFuncSetAttribute(hgemm<true,  1, 2>, cudaFuncAttributeMaxDynamicSharedMemorySize, GEMM_SMEM);
    cudaFuncSetAttribute(hgemm<false, 3, 0>, cudaFuncAttributeMaxDynamicSharedMemorySize, GEMM_SMEM);
    cudaFuncSetAttribute(hgemm<true,  1, 3>, cudaFuncAttributeMaxDynamicSharedMemorySize, GEMM_SMEM);
    cudaFuncSetAttribute(hgemm<true,  1, 0>, cudaFuncAttributeMaxDynamicSharedMemorySize, GEMM_SMEM);

    // ---- 1. prep: splits + bias gather ----
    {
        const unsigned nb = (unsigned)(NBF / 4 / 256);
        split_kernel<<<nb, 256>>>(queries, INH,           INL);
        split_kernel<<<nb, 256>>>(keys,    INH + NBF,     INL + NBF);
        conv_hi_kernel<<<nb, 256>>>(values, INH + 2 * NBF);
        const unsigned nw = (unsigned)(DD / 4 / 256);
        split_kernel<<<nw, 256>>>(Wq, Wt + 0 * DD, Wt + 1 * DD);
        split_kernel<<<nw, 256>>>(Wk, Wt + 2 * DD, Wt + 3 * DD);
        conv_hi_kernel<<<nw, 256>>>(Wv, Wt + 4 * DD);
        conv_hi_kernel<<<nw, 256>>>(Wg, Wt + 5 * DD);
        conv_hi_kernel<<<nw, 256>>>(Wo, Wt + 6 * DD);
        gather_bias_kernel<<<4, 256>>>(bq, bk, bv, bg, BIA);
    }

    // ---- 2a. fused Q+K projections (3-pass, pair out): z selects problem ----
    {
        dim3 g(DIM / 128, MTOT / 128, 2);
        hgemm<true, 3, 1><<<g, 128, GEMM_SMEM>>>(
            INH, INL,                         // A: queries / keys (stride NBF)
            Wt + 0 * DD, Wt + 1 * DD,         // B: Wq pair / Wk pair (stride 2*DD)
            nullptr, QKH, QKL, BIA,
            DIM, DIM, DIM, DIM,
            (long long)NBF, (long long)(2 * DD), (long long)NBF, DIM);
    }

    // ---- 2b. fused V+G projections (1-pass, hi out) ----
    {
        dim3 g(DIM / 128, MTOT / 128, 2);
        hgemm<true, 1, 2><<<g, 128, GEMM_SMEM>>>(
            INH + 2 * NBF, nullptr,           // z0: values, z1: queries (stride -2*NBF)
            Wt + 4 * DD, nullptr,             // z0: Wvh, z1: Wgh (stride DD)
            nullptr, VGH, nullptr, BIA + 2 * DIM,
            DIM, DIM, DIM, DIM,
            -(long long)(2 * NBF), (long long)DD, (long long)NBF, DIM);
    }

    // ---- 3. scores[b] = q[b] @ k[b]^T (3-pass) ----
    {
        dim3 g(SEQ / 128, SEQ / 128, BATCH);
        hgemm<false, 3, 0><<<g, 128, GEMM_SMEM>>>(
            QKH, QKL,                         // q pair
            QKH + NBF, QKL + NBF,             // k pair
            (float*)scores, nullptr, nullptr, nullptr,
            DIM, DIM, SEQ, DIM,
            (long long)SEQ * DIM, (long long)SEQ * DIM, (long long)SEQ * SEQ, 0);
    }

    // ---- 4. softmax -> fp16 hi ----
    softmax_h_kernel<<<BATCH * SEQ, 256>>>((const float*)scores, (__half*)ah);

    // ---- 5. gated ctx = (attn @ v) * sigmoid(gpre)  (1-pass, fused gate) ----
    {
        dim3 g(DIM / 128, SEQ / 128, BATCH);
        hgemm<true, 1, 3><<<g, 128, GEMM_SMEM>>>(
            (const __half*)ah, nullptr,
            VGH, nullptr,                     // v-proj hi, [k][n]
            nullptr, (__half*)gch, VGH + NBF, // out gch; gpre read via cl
            nullptr,
            SEQ, DIM, DIM, SEQ,
            (long long)SEQ * SEQ, (long long)SEQ * DIM, (long long)SEQ * DIM, 0);
    }

    // ---- 6. out = gated @ Wo + bo (1-pass) ----
    {
        dim3 g(DIM / 128, MTOT / 128, 1);
        hgemm<true, 1, 0><<<g, 128, GEMM_SMEM>>>(
            (const __half*)gch, nullptr,
            Wt + 6 * DD, nullptr,
            out, nullptr, nullptr, bo,
            DIM, DIM, DIM, DIM, 0, 0, 0, 0);
    }
}

// round 14
// speedup vs baseline: 1.8227x; 1.0802x over previous
#include <cuda_runtime.h>
#include <cuda_fp16.h>
#include <math.h>
#include <stdint.h>

#define BATCH 8
#define SEQ   2048
#define DIM   1024
#define MTOT  (BATCH * SEQ)   // 16384
#define DD    ((size_t)DIM * DIM)

#define NBF ((size_t)MTOT * DIM)         // 16,777,216
#define NSC ((size_t)BATCH * SEQ * SEQ)  // 33,554,432

// ===================== scratch (no cudaMalloc allowed) =====================
__device__ __align__(1024) __half g_inh[3 * NBF];   // hi: [0]=queries [1]=keys [2]=values
__device__ __align__(1024) __half g_inl[2 * NBF];   // lo: [0]=queries [1]=keys
__device__ __align__(1024) __half g_qkph[2 * NBF];  // [0]=q-proj hi, [1]=k-proj hi
__device__ __align__(1024) __half g_qkpl[2 * NBF];  // [0]=q-proj lo, [1]=k-proj lo
__device__ __align__(1024) __half g_vgh[2 * NBF];   // [0]=v-proj hi, [1]=gpre hi
__device__ __align__(1024) __half g_gch[NBF];       // gated context hi
__device__ __align__(1024) __half g_ah[NSC];        // softmax(attn) hi
__device__ __align__(1024) __half g_W[7 * DD];      // 0=Wqh 1=Wql 2=Wkh 3=Wkl 4=Wvh 5=Wgh 6=Woh
__device__ __align__(1024) float g_scores[NSC];
__device__ __align__(1024) float g_bias[4 * DIM];   // 0=bq 1=bk 2=bv 3=bg

// ===================== PTX wrappers =====================
__device__ __forceinline__ uint32_t smem_u32(const void* p) {
    uint32_t a;
    asm("{ .reg .u64 t; cvta.to.shared.u64 t, %1; cvt.u32.u64 %0, t; }" : "=r"(a) : "l"(p));
    return a;
}
__device__ __forceinline__ void cpa16(uint32_t dst, const void* src) {
    asm volatile("cp.async.cg.shared.global [%0], [%1], 16;" :: "r"(dst), "l"(src));
}
__device__ __forceinline__ void cp_commit() {
    asm volatile("cp.async.commit_group;" ::: "memory");
}
template <int N>
__device__ __forceinline__ void cp_wait() {
    asm volatile("cp.async.wait_group %0;" :: "n"(N) : "memory");
}
__device__ __forceinline__ void ldm4(uint32_t r[4], uint32_t addr) {
    asm volatile("ldmatrix.sync.aligned.m8n8.x4.shared.b16 {%0,%1,%2,%3}, [%4];"
                 : "=r"(r[0]), "=r"(r[1]), "=r"(r[2]), "=r"(r[3]) : "r"(addr));
}
__device__ __forceinline__ void ldm4t(uint32_t r[4], uint32_t addr) {
    asm volatile("ldmatrix.sync.aligned.m8n8.x4.trans.shared.b16 {%0,%1,%2,%3}, [%4];"
                 : "=r"(r[0]), "=r"(r[1]), "=r"(r[2]), "=r"(r[3]) : "r"(addr));
}
__device__ __forceinline__ void mma16816(float c[4],
                                         const uint32_t a[4],
                                         uint32_t b0, uint32_t b1) {
    asm volatile(
        "mma.sync.aligned.m16n8k16.row.col.f32.f16.f16.f32 "
        "{%0,%1,%2,%3}, {%4,%5,%6,%7}, {%8,%9}, {%0,%1,%2,%3};"
        : "+f"(c[0]), "+f"(c[1]), "+f"(c[2]), "+f"(c[3])
        : "r"(a[0]), "r"(a[1]), "r"(a[2]), "r"(a[3]), "r"(b0), "r"(b1));
}
__device__ __forceinline__ void split2h(float x, __half& h, __half& l) {
    h = __float2half_rn(x);
    l = __float2half_rn(x - __half2float(h));
}
__device__ __forceinline__ float sigmoidf_(float x) {
    return 1.0f / (1.0f + expf(-x));
}

// ===================== fp16 split HMMA GEMM =====================
// CTA tile 128x128, 128 threads / 4 warps, warp tile 64x64.
// NPASS=3: Ah*Bh + Ah*Bl + Al*Bh  (4 smem slots/stage, 2 stages, wait<0>)
// NPASS=2: Ah*Bh + Ah*Bl          (3 slots/stage, 2 stages)
// NPASS=1: Ah*Bh                  (2 slots/stage, 3 stages, wait<1> lookahead)
// TRANSB=false: B stored [n][k]. TRANSB=true: B stored [k][n].
// OMODE 0: fp32 out (+bias). OMODE 1: fp16 hi/lo pair (+bias). OMODE 2: fp16 hi (+bias).
// OMODE 3: gated fp16 hi: val * sigmoid(gpre_h), gpre_h passed via cl.
// blockIdx.z strides all pointers; bias += z*sbias.
#define PA_E   40
#define PA_B   (PA_E * 2)    // 80 bytes
#define PBT_E  136
#define PBT_B  (PBT_E * 2)   // 272 bytes
#define MAT_BYTES   10240

template <int NPASS> struct GemmCfg {
    static constexpr int A_SLOTS = (NPASS == 3) ? 2 : 1;
    static constexpr int B_SLOTS = (NPASS >= 2) ? 2 : 1;
    static constexpr int STAGE   = (A_SLOTS + B_SLOTS) * MAT_BYTES;
    static constexpr int NST     = (NPASS == 1) ? 3 : 2;
    static constexpr int SMEM    = NST * STAGE;
};

template <bool TRANSB, int NPASS, int OMODE>
__global__ void __launch_bounds__(128, 2)
hgemm(const __half* __restrict__ gAh, const __half* __restrict__ gAl,
      const __half* __restrict__ gBh, const __half* __restrict__ gBl,
      float* __restrict__ cf,
      __half* __restrict__ ch, __half* __restrict__ cl,
      const float* __restrict__ bias,
      int lda, int ldb, int ldc, int K,
      long long sa, long long sb, long long sc, int sbias)
{
    using CFG = GemmCfg<NPASS>;
    extern __shared__ __align__(128) char smem[];
    const uint32_t sbase = smem_u32(smem);

    const int tid  = threadIdx.x;
    const int wid  = tid >> 5;
    const int lane = tid & 31;
    const int m0   = blockIdx.y * 128;
    const int n0   = blockIdx.x * 128;
    const int z    = blockIdx.z;

    gAh += (long long)z * sa;
    if (NPASS == 3) gAl += (long long)z * sa;
    gBh += (long long)z * sb;
    if (NPASS >= 2) gBl += (long long)z * sb;
    if (bias) bias += (long long)z * sbias;

    const int wm0 = (wid >> 1) * 64;
    const int wn0 = (wid & 1) * 64;

    float acc[4][8][4];
    #pragma unroll
    for (int i = 0; i < 4; i++)
        #pragma unroll
        for (int j = 0; j < 8; j++)
            #pragma unroll
            for (int r = 0; r < 4; r++) acc[i][j][r] = 0.0f;

    const int nchunks = K >> 5;

    // ------- stage loader (128 threads) -------
    auto load_stage = [&](int s, int k0) {
        const uint32_t st = sbase + s * CFG::STAGE;
        const uint32_t bst = st + CFG::A_SLOTS * MAT_BYTES;
        #pragma unroll
        for (int j = 0; j < 4; j++) {
            const int c = tid + 128 * j;
            {   // A: 128 rows x 32 cols
                const int row = c >> 2, col = c & 3;
                const uint32_t so = st + row * PA_B + col * 16;
                const long long go = (long long)(m0 + row) * lda + k0 + col * 8;
                cpa16(so, gAh + go);
                if (NPASS == 3) cpa16(so + MAT_BYTES, gAl + go);
            }
            if (TRANSB) {   // B: 32 rows (k) x 128 cols (n)
                const int row = c >> 4, col = c & 15;
                const uint32_t so = bst + row * PBT_B + col * 16;
                const long long go = (long long)(k0 + row) * ldb + n0 + col * 8;
                cpa16(so, gBh + go);
                if (NPASS >= 2) cpa16(so + MAT_BYTES, gBl + go);
            } else {        // B: 128 rows (n) x 32 cols (k)
                const int row = c >> 2, col = c & 3;
                const uint32_t so = bst + row * PA_B + col * 16;
                const long long go = (long long)(n0 + row) * ldb + k0 + col * 8;
                cpa16(so, gBh + go);
                if (NPASS >= 2) cpa16(so + MAT_BYTES, gBl + go);
            }
        }
    };

    // ------- compute one stage -------
    auto compute_stage = [&](int s) {
        const uint32_t ab = sbase + s * CFG::STAGE;
        const uint32_t bb = ab + CFG::A_SLOTS * MAT_BYTES;
        #pragma unroll
        for (int ks = 0; ks < 32; ks += 16) {
            uint32_t ah[4][4], al[4][4];
            #pragma unroll
            for (int im = 0; im < 4; im++) {
                const uint32_t addr = ab
                    + (wm0 + im * 16 + (lane & 15)) * PA_B
                    + (ks + ((lane >> 4) << 3)) * 2;
                ldm4(ah[im], addr);
                if (NPASS == 3) ldm4(al[im], addr + MAT_BYTES);
            }
            #pragma unroll
            for (int half = 0; half < 4; half++) {
                const int nb = wn0 + half * 16;
                uint32_t rh[4], rl[4];
                if (TRANSB) {
                    const int krow = ks + (lane & 7) + (((lane >> 3) & 1) << 3);
                    const int ncol = nb + ((lane >> 4) << 3);
                    const uint32_t addr = bb + krow * PBT_B + ncol * 2;
                    ldm4t(rh, addr);
                    if (NPASS >= 2) ldm4t(rl, addr + MAT_BYTES);
                } else {
                    const int nrow = nb + (lane & 7) + ((lane >> 4) << 3);
                    const int kcol = ks + (((lane >> 3) & 1) << 3);
                    const uint32_t addr = bb + nrow * PA_B + kcol * 2;
                    ldm4(rh, addr);
                    if (NPASS >= 2) ldm4(rl, addr + MAT_BYTES);
                }
                #pragma unroll
                for (int im = 0; im < 4; im++) {
                    mma16816(acc[im][2*half],   ah[im], rh[0], rh[1]);
                    if (NPASS >= 2) mma16816(acc[im][2*half], ah[im], rl[0], rl[1]);
                    if (NPASS == 3) mma16816(acc[im][2*half], al[im], rh[0], rh[1]);
                    mma16816(acc[im][2*half+1], ah[im], rh[2], rh[3]);
                    if (NPASS >= 2) mma16816(acc[im][2*half+1], ah[im], rl[2], rl[3]);
                    if (NPASS == 3) mma16816(acc[im][2*half+1], al[im], rh[2], rh[3]);
                }
            }
        }
    };

    // ------- pipeline -------
    // NST=2: wait<0> -> sync -> load(c+1) -> compute(c)
    // NST=3: prologue loads c=0,1; wait<1> keeps one chunk of lookahead in flight.
    load_stage(0, 0);
    cp_commit();
    if (CFG::NST == 3 && nchunks > 1) { load_stage(1, 32); cp_commit(); }
    for (int c = 0; c < nchunks; c++) {
        const int next = c + CFG::NST - 1;
        if (CFG::NST == 3) {
            if (next < nchunks) cp_wait<1>(); else cp_wait<0>();
        } else {
            cp_wait<0>();
        }
        __syncthreads();
        if (next < nchunks) { load_stage(next % CFG::NST, next * 32); cp_commit(); }
        compute_stage(c % CFG::NST);
    }

    // ------- epilogue -------
    const long long zc = (long long)z * sc;
    #pragma unroll
    for (int im = 0; im < 4; im++) {
        #pragma unroll
        for (int in = 0; in < 8; in++) {
            const int mr = m0 + wm0 + im * 16 + (lane >> 2);
            const int nc = n0 + wn0 + in * 8 + ((lane & 3) << 1);
            float bx = 0.0f, by = 0.0f;
            if (OMODE != 3 && bias) {
                float2 bb = *reinterpret_cast<const float2*>(&bias[nc]);
                bx = bb.x; by = bb.y;
            }
            float v0 = acc[im][in][0] + bx;
            float v1 = acc[im][in][1] + by;
            float v2 = acc[im][in][2] + bx;
            float v3 = acc[im][in][3] + by;
            const long long o0 = zc + (long long)mr * ldc + nc;
            const long long o1 = zc + (long long)(mr + 8) * ldc + nc;
            if (OMODE == 0) {
                *reinterpret_cast<float2*>(&cf[o0]) = make_float2(v0, v1);
                *reinterpret_cast<float2*>(&cf[o1]) = make_float2(v2, v3);
            } else if (OMODE == 2 || OMODE == 3) {
                if (OMODE == 3) {
                    __half2 g01 = *reinterpret_cast<const __half2*>(&cl[o0]);
                    __half2 g23 = *reinterpret_cast<const __half2*>(&cl[o1]);
                    v0 *= sigmoidf_(__half2float(g01.x));
                    v1 *= sigmoidf_(__half2float(g01.y));
                    v2 *= sigmoidf_(__half2float(g23.x));
                    v3 *= sigmoidf_(__half2float(g23.y));
                }
                *reinterpret_cast<__half2*>(&ch[o0]) =
                    __halves2half2(__float2half_rn(v0), __float2half_rn(v1));
                *reinterpret_cast<__half2*>(&ch[o1]) =
                    __halves2half2(__float2half_rn(v2), __float2half_rn(v3));
            } else {
                __half h0, l0, h1, l1, h2, l2, h3, l3;
                split2h(v0, h0, l0); split2h(v1, h1, l1);
                split2h(v2, h2, l2); split2h(v3, h3, l3);
                *reinterpret_cast<__half2*>(&ch[o0]) = __halves2half2(h0, h1);
                *reinterpret_cast<__half2*>(&ch[o1]) = __halves2half2(h2, h3);
                *reinterpret_cast<__half2*>(&cl[o0]) = __halves2half2(l0, l1);
                *reinterpret_cast<__half2*>(&cl[o1]) = __halves2half2(l2, l3);
            }
        }
    }
}

// ===================== glue kernels =====================
// fused input split: z=0 queries(pair), z=1 keys(pair), z=2 values(hi only)
__global__ __launch_bounds__(256)
void split_inputs_kernel(const float* __restrict__ q, const float* __restrict__ k,
                         const float* __restrict__ v,
                         __half* __restrict__ hi, __half* __restrict__ lo)
{
    const int z = blockIdx.y;
    const float* src = (z == 0) ? q : (z == 1) ? k : v;
    const size_t i = ((size_t)blockIdx.x * 256 + threadIdx.x) * 4;
    float4 x = *reinterpret_cast<const float4*>(src + i);
    const size_t o = (size_t)z * NBF + i;
    if (z < 2) {
        __half h0,l0,h1,l1,h2,l2,h3,l3;
        split2h(x.x, h0, l0); split2h(x.y, h1, l1); split2h(x.z, h2, l2); split2h(x.w, h3, l3);
        *reinterpret_cast<__half2*>(hi + o)     = __halves2half2(h0, h1);
        *reinterpret_cast<__half2*>(hi + o + 2) = __halves2half2(h2, h3);
        *reinterpret_cast<__half2*>(lo + o)     = __halves2half2(l0, l1);
        *reinterpret_cast<__half2*>(lo + o + 2) = __halves2half2(l2, l3);
    } else {
        *reinterpret_cast<__half2*>(hi + o)     = __halves2half2(__float2half_rn(x.x), __float2half_rn(x.y));
        *reinterpret_cast<__half2*>(hi + o + 2) = __halves2half2(__float2half_rn(x.z), __float2half_rn(x.w));
    }
}

__global__ __launch_bounds__(256)
void split_kernel(const float* __restrict__ src,
                  __half* __restrict__ hi, __half* __restrict__ lo)
{
    const size_t i = ((size_t)blockIdx.x * 256 + threadIdx.x) * 4;
    float4 v = *reinterpret_cast<const float4*>(src + i);
    __half h0,l0,h1,l1,h2,l2,h3,l3;
    split2h(v.x, h0, l0); split2h(v.y, h1, l1); split2h(v.z, h2, l2); split2h(v.w, h3, l3);
    *reinterpret_cast<__half2*>(hi + i)     = __halves2half2(h0, h1);
    *reinterpret_cast<__half2*>(hi + i + 2) = __halves2half2(h2, h3);
    *reinterpret_cast<__half2*>(lo + i)     = __halves2half2(l0, l1);
    *reinterpret_cast<__half2*>(lo + i + 2) = __halves2half2(l2, l3);
}

__global__ __launch_bounds__(256)
void conv_hi_kernel(const float* __restrict__ src, __half* __restrict__ hi)
{
    const size_t i = ((size_t)blockIdx.x * 256 + threadIdx.x) * 4;
    float4 v = *reinterpret_cast<const float4*>(src + i);
    *reinterpret_cast<__half2*>(hi + i)     = __halves2half2(__float2half_rn(v.x), __float2half_rn(v.y));
    *reinterpret_cast<__half2*>(hi + i + 2) = __halves2half2(__float2half_rn(v.z), __float2half_rn(v.w));
}

__global__ __launch_bounds__(256)
void gather_bias_kernel(const float* __restrict__ b0, const float* __restrict__ b1,
                        const float* __restrict__ b2, const float* __restrict__ b3,
                        float* __restrict__ out)
{
    const int v = blockIdx.x;
    const float* src = (v == 0) ? b0 : (v == 1) ? b1 : (v == 2) ? b2 : b3;
    for (int j = threadIdx.x; j < DIM; j += 256) out[(size_t)v * DIM + j] = src[j];
}

// row softmax (len 2048) -> fp16 hi
__global__ __launch_bounds__(256)
void softmax_h_kernel(const float* __restrict__ S, __half* __restrict__ ah)
{
    const size_t row = blockIdx.x;
    const float4* p4 = reinterpret_cast<const float4*>(S + row * SEQ);
    const int tid = threadIdx.x;
    __shared__ float red[8];

    float4 v[2];
    float mx = -1e30f;
    #pragma unroll
    for (int i = 0; i < 2; i++) {
        v[i] = p4[i * 256 + tid];
        mx = fmaxf(mx, fmaxf(fmaxf(v[i].x, v[i].y), fmaxf(v[i].z, v[i].w)));
    }
    #pragma unroll
    for (int o = 16; o; o >>= 1) mx = fmaxf(mx, __shfl_xor_sync(0xffffffffu, mx, o));
    if ((tid & 31) == 0) red[tid >> 5] = mx;
    __syncthreads();
    mx = red[0];
    #pragma unroll
    for (int i = 1; i < 8; i++) mx = fmaxf(mx, red[i]);
    __syncthreads();

    float s = 0.0f;
    #pragma unroll
    for (int i = 0; i < 2; i++) {
        v[i].x = expf(v[i].x - mx); v[i].y = expf(v[i].y - mx);
        v[i].z = expf(v[i].z - mx); v[i].w = expf(v[i].w - mx);
        s += v[i].x + v[i].y + v[i].z + v[i].w;
    }
    #pragma unroll
    for (int o = 16; o; o >>= 1) s += __shfl_xor_sync(0xffffffffu, s, o);
    if ((tid & 31) == 0) red[tid >> 5] = s;
    __syncthreads();
    s = red[0];
    #pragma unroll
    for (int i = 1; i < 8; i++) s += red[i];

    const float inv = 1.0f / s;
    #pragma unroll
    for (int i = 0; i < 2; i++) {
        const size_t e = row * SEQ + ((size_t)i * 256 + tid) * 4;
        *reinterpret_cast<__half2*>(ah + e) =
            __halves2half2(__float2half_rn(v[i].x * inv), __float2half_rn(v[i].y * inv));
        *reinterpret_cast<__half2*>(ah + e + 2) =
            __halves2half2(__float2half_rn(v[i].z * inv), __float2half_rn(v[i].w * inv));
    }
}

// ===================== host =====================
extern "C" void kernel_launch(void* const* d_in, const int* in_sizes, int n_in,
                              void* d_out, int out_size)
{
    (void)in_sizes; (void)n_in; (void)out_size;

    const float* queries = (const float*)d_in[0];
    const float* keys    = (const float*)d_in[1];
    const float* values  = (const float*)d_in[2];
    const float* Wq = (const float*)d_in[3];
    const float* bq = (const float*)d_in[4];
    const float* Wk = (const float*)d_in[5];
    const float* bk = (const float*)d_in[6];
    const float* Wv = (const float*)d_in[7];
    const float* bv = (const float*)d_in[8];
    const float* Wg = (const float*)d_in[9];
    const float* bg = (const float*)d_in[10];
    const float* Wo = (const float*)d_in[11];
    const float* bo = (const float*)d_in[12];
    float* out = (float*)d_out;

    void *inh, *inl, *qkph, *qkpl, *vgh, *gch, *ah, *scores, *Wbase, *biasb;
    cudaGetSymbolAddress(&inh, g_inh);   cudaGetSymbolAddress(&inl, g_inl);
    cudaGetSymbolAddress(&qkph, g_qkph); cudaGetSymbolAddress(&qkpl, g_qkpl);
    cudaGetSymbolAddress(&vgh, g_vgh);   cudaGetSymbolAddress(&gch, g_gch);
    cudaGetSymbolAddress(&ah, g_ah);     cudaGetSymbolAddress(&scores, g_scores);
    cudaGetSymbolAddress(&Wbase, g_W);   cudaGetSymbolAddress(&biasb, g_bias);
    __half* INH = (__half*)inh;  __half* INL = (__half*)inl;
    __half* QKH = (__half*)qkph; __half* QKL = (__half*)qkpl;
    __half* VGH = (__half*)vgh;
    __half* Wt  = (__half*)Wbase;
    float*  BIA = (float*)biasb;

    const int SMEM3 = GemmCfg<3>::SMEM;   // 81920
    const int SMEM1 = GemmCfg<1>::SMEM;   // 61440

    cudaFuncSetAttribute(hgemm<true,  3, 1>, cudaFuncAttributeMaxDynamicSharedMemorySize, SMEM3);
    cudaFuncSetAttribute(hgemm<false, 3, 0>, cudaFuncAttributeMaxDynamicSharedMemorySize, SMEM3);
    cudaFuncSetAttribute(hgemm<true,  1, 2>, cudaFuncAttributeMaxDynamicSharedMemorySize, SMEM1);
    cudaFuncSetAttribute(hgemm<true,  1, 3>, cudaFuncAttributeMaxDynamicSharedMemorySize, SMEM1);
    cudaFuncSetAttribute(hgemm<true,  1, 0>, cudaFuncAttributeMaxDynamicSharedMemorySize, SMEM1);

    // ---- 1. prep: fused input splits + weight converts + bias gather ----
    {
        dim3 gi((unsigned)(NBF / 4 / 256), 3);
        split_inputs_kernel<<<gi, 256>>>(queries, keys, values, INH, INL);
        const unsigned nw = (unsigned)(DD / 4 / 256);
        split_kernel<<<nw, 256>>>(Wq, Wt + 0 * DD, Wt + 1 * DD);
        split_kernel<<<nw, 256>>>(Wk, Wt + 2 * DD, Wt + 3 * DD);
        conv_hi_kernel<<<nw, 256>>>(Wv, Wt + 4 * DD);
        conv_hi_kernel<<<nw, 256>>>(Wg, Wt + 5 * DD);
        conv_hi_kernel<<<nw, 256>>>(Wo, Wt + 6 * DD);
        gather_bias_kernel<<<4, 256>>>(bq, bk, bv, bg, BIA);
    }

    // ---- 2a. fused Q+K projections (3-pass, pair out) ----
    {
        dim3 g(DIM / 128, MTOT / 128, 2);
        hgemm<true, 3, 1><<<g, 128, SMEM3>>>(
            INH, INL,
            Wt + 0 * DD, Wt + 1 * DD,
            nullptr, QKH, QKL, BIA,
            DIM, DIM, DIM, DIM,
            (long long)NBF, (long long)(2 * DD), (long long)NBF, DIM);
    }

    // ---- 2b. fused V+G projections (1-pass, hi out) ----
    {
        dim3 g(DIM / 128, MTOT / 128, 2);
        hgemm<true, 1, 2><<<g, 128, SMEM1>>>(
            INH + 2 * NBF, nullptr,           // z0: values, z1: queries (stride -2*NBF)
            Wt + 4 * DD, nullptr,             // z0: Wvh, z1: Wgh (stride DD)
            nullptr, VGH, nullptr, BIA + 2 * DIM,
            DIM, DIM, DIM, DIM,
            -(long long)(2 * NBF), (long long)DD, (long long)NBF, DIM);
    }

    // ---- 3. scores[b] = q[b] @ k[b]^T (3-pass) ----
    {
        dim3 g(SEQ / 128, SEQ / 128, BATCH);
        hgemm<false, 3, 0><<<g, 128, SMEM3>>>(
            QKH, QKL,
            QKH + NBF, QKL + NBF,
            (float*)scores, nullptr, nullptr, nullptr,
            DIM, DIM, SEQ, DIM,
            (long long)SEQ * DIM, (long long)SEQ * DIM, (long long)SEQ * SEQ, 0);
    }

    // ---- 4. softmax -> fp16 hi ----
    softmax_h_kernel<<<BATCH * SEQ, 256>>>((const float*)scores, (__half*)ah);

    // ---- 5. gated ctx = (attn @ v) * sigmoid(gpre)  (1-pass, fused gate) ----
    {
        dim3 g(DIM / 128, SEQ / 128, BATCH);
        hgemm<true, 1, 3><<<g, 128, SMEM1>>>(
            (const __half*)ah, nullptr,
            VGH, nullptr,
            nullptr, (__half*)gch, VGH + NBF,
            nullptr,
            SEQ, DIM, DIM, SEQ,
            (long long)SEQ * SEQ, (long long)SEQ * DIM, (long long)SEQ * DIM, 0);
    }

    // ---- 6. out = gated @ Wo + bo (1-pass) ----
    {
        dim3 g(DIM / 128, MTOT / 128, 1);
        hgemm<true, 1, 0><<<g, 128, SMEM1>>>(
            (const __half*)gch, nullptr,
            Wt + 6 * DD, nullptr,
            out, nullptr, nullptr, bo,
            DIM, DIM, DIM, DIM, 0, 0, 0, 0);
    }
}